// round 1
// baseline (speedup 1.0000x reference)
#include <cuda_runtime.h>
#include <math.h>

#define BDIM 512
#define SLEN 2048
#define BATCH 32
#define NROWS (BATCH*SLEN)
#define KS 19
#define NC 32                    // NCLS * H
#define LOGS 7.6246189861594f    // log(2048)

// ---------------- scratch (static device globals; no allocs) ----------------
__device__ float g_Wc[BDIM*KS];                    // combined wavelet kernel [d][t]
__device__ float g_qfull[2*BDIM];                  // q rows [n][512]
__device__ float g_WqT[NC*BDIM];                   // WqEff transposed [c][d], scale folded
__device__ float g_pos[(size_t)NROWS*BDIM];        // conv output
__device__ float g_x2[(size_t)NROWS*BDIM];         // x + pos@Wp1 + bp1
__device__ float g_stats[NROWS*2];                 // per-row mean, rstd
__device__ float g_Ppart[BATCH*4*NC*BDIM];         // pooling partials [b][schunk][c][d]
__device__ float g_A[BATCH*NC];                    // sum attn
__device__ float g_Mw[BATCH*NC];                   // sum attn*rstd*mean
__device__ float g_pooled[BATCH*NC*BDIM];          // pooled xn [b][c][d]
__device__ float g_ohead[BATCH*2*BDIM];            // o before Wproj
__device__ float g_o[BATCH*2*BDIM];                // o after Wproj

// ---------------- tiny precompute kernels ----------------
__global__ void k_qfull(const float* __restrict__ cls, const float* __restrict__ Wq) {
    int n = blockIdx.x, j = threadIdx.x;
    float acc = 0.f;
    #pragma unroll 8
    for (int d = 0; d < BDIM; d++) acc += cls[n*BDIM + d] * Wq[(size_t)d*BDIM + j];
    g_qfull[n*BDIM + j] = acc;
}

__global__ void k_weff(const float* __restrict__ Wkv) {
    int c = blockIdx.x, d = threadIdx.x;     // c = n*16 + h
    int n = c >> 4, h = c & 15;
    float acc = 0.f;
    #pragma unroll
    for (int hd = 0; hd < 32; hd++)
        acc += Wkv[(size_t)d*1024 + h*32 + hd] * g_qfull[n*BDIM + h*32 + hd];
    g_WqT[c*BDIM + d] = acc * 0.17677669529663689f;  // * HD^-0.5
}

__global__ void k_wavelet(const float* __restrict__ w1, const float* __restrict__ w2,
                          const float* __restrict__ w3) {
    int d = threadIdx.x, t = blockIdx.x;
    const float C = 0.8673250705840776f;     // 2 / (sqrt(3) * pi^0.25)
    float xs = (float)(t - 9);
    const float* ws[3] = {w1, w2, w3};
    float sum = 0.f;
    #pragma unroll
    for (int i = 0; i < 3; i++) {
        float scale = ws[i][d];
        float shift = ws[i][BDIM + d];
        float u = (xs - shift) / scale;
        sum += C * (1.f - u*u) * expf(-0.5f*u*u) * rsqrtf(fabsf(scale));
    }
    g_Wc[d*KS + t] = sum;
}

// ---------------- depthwise conv (summed kernel) ----------------
__global__ void k_conv(const float* __restrict__ x) {
    int row = blockIdx.x;                  // b*S + s
    int d   = threadIdx.x;
    int s   = row & (SLEN - 1);
    float acc = 0.f;
    #pragma unroll
    for (int t = 0; t < KS; t++) {
        int ss = s + t - 9;
        if (ss >= 0 && ss < SLEN)
            acc += x[(size_t)(row + t - 9)*BDIM + d] * g_Wc[d*KS + t];
    }
    g_pos[(size_t)row*BDIM + d] = acc;
}

// ---------------- x2 = x + pos @ Wp1 + bp1  (128x128x16 fp32 tiles) ----------------
__global__ __launch_bounds__(256) void k_gemm_wp1(const float* __restrict__ x,
                                                  const float* __restrict__ Wp1,
                                                  const float* __restrict__ bp1) {
    __shared__ float As[16][128];
    __shared__ float Bs[16][128];
    int tid = threadIdx.x;
    int m0 = blockIdx.y * 128;
    int n0 = blockIdx.x * 128;
    float acc[8][8];
    #pragma unroll
    for (int i = 0; i < 8; i++)
        #pragma unroll
        for (int j = 0; j < 8; j++) acc[i][j] = 0.f;

    int tx = tid & 15, ty = tid >> 4;
    int lr = tid >> 1, lk = (tid & 1) * 8;     // A load slot
    int kk = tid >> 4, nn = (tid & 15) * 8;    // B load slot
    const float* pA = &g_pos[(size_t)(m0 + lr)*BDIM + lk];

    for (int k0 = 0; k0 < BDIM; k0 += 16) {
        float4 a0 = *(const float4*)(pA + k0);
        float4 a1 = *(const float4*)(pA + k0 + 4);
        const float* pB = &Wp1[(size_t)(k0 + kk)*BDIM + n0 + nn];
        float4 b0 = *(const float4*)(pB);
        float4 b1 = *(const float4*)(pB + 4);
        As[lk+0][lr] = a0.x; As[lk+1][lr] = a0.y; As[lk+2][lr] = a0.z; As[lk+3][lr] = a0.w;
        As[lk+4][lr] = a1.x; As[lk+5][lr] = a1.y; As[lk+6][lr] = a1.z; As[lk+7][lr] = a1.w;
        *(float4*)&Bs[kk][nn]     = b0;
        *(float4*)&Bs[kk][nn + 4] = b1;
        __syncthreads();
        #pragma unroll
        for (int k = 0; k < 16; k++) {
            float4 av0 = *(float4*)&As[k][ty*8];
            float4 av1 = *(float4*)&As[k][ty*8 + 4];
            float4 bv0 = *(float4*)&Bs[k][tx*8];
            float4 bv1 = *(float4*)&Bs[k][tx*8 + 4];
            float a[8] = {av0.x, av0.y, av0.z, av0.w, av1.x, av1.y, av1.z, av1.w};
            float b[8] = {bv0.x, bv0.y, bv0.z, bv0.w, bv1.x, bv1.y, bv1.z, bv1.w};
            #pragma unroll
            for (int i = 0; i < 8; i++)
                #pragma unroll
                for (int j = 0; j < 8; j++) acc[i][j] += a[i]*b[j];
        }
        __syncthreads();
    }
    #pragma unroll
    for (int i = 0; i < 8; i++) {
        size_t row = (size_t)(m0 + ty*8 + i);
        #pragma unroll
        for (int j4 = 0; j4 < 2; j4++) {
            int col = n0 + tx*8 + j4*4;
            float4 xv = *(const float4*)&x[row*BDIM + col];
            float4 bv = *(const float4*)&bp1[col];
            float4 o;
            o.x = xv.x + acc[i][j4*4+0] + bv.x;
            o.y = xv.y + acc[i][j4*4+1] + bv.y;
            o.z = xv.z + acc[i][j4*4+2] + bv.z;
            o.w = xv.w + acc[i][j4*4+3] + bv.w;
            *(float4*)&g_x2[row*BDIM + col] = o;
        }
    }
}

// ---------------- LN stats + scores + sigmoid -> attn output ----------------
__global__ __launch_bounds__(256) void k_scores(const float* __restrict__ ln_g,
                                                const float* __restrict__ ln_b,
                                                float* __restrict__ attn_out) {
    __shared__ float red[8][32][33];
    int w    = threadIdx.x >> 5;
    int lane = threadIdx.x & 31;
    int row  = blockIdx.x*8 + w;
    int dbase = lane*16;
    const float* xr = &g_x2[(size_t)row*BDIM + dbase];

    float xv[16];
    #pragma unroll
    for (int i4 = 0; i4 < 4; i4++) {
        float4 v = *(const float4*)(xr + i4*4);
        xv[i4*4+0] = v.x; xv[i4*4+1] = v.y; xv[i4*4+2] = v.z; xv[i4*4+3] = v.w;
    }
    float sum = 0.f, sq = 0.f;
    #pragma unroll
    for (int i = 0; i < 16; i++) { sum += xv[i]; sq += xv[i]*xv[i]; }
    #pragma unroll
    for (int off = 16; off; off >>= 1) {
        sum += __shfl_xor_sync(0xffffffffu, sum, off);
        sq  += __shfl_xor_sync(0xffffffffu, sq,  off);
    }
    float mean = sum * (1.f/512.f);
    float var  = sq  * (1.f/512.f) - mean*mean;
    float rstd = rsqrtf(var + 1e-5f);
    if (lane == 0) { g_stats[row*2] = mean; g_stats[row*2+1] = rstd; }

    float xn[16];
    #pragma unroll
    for (int i4 = 0; i4 < 4; i4++) {
        float4 g = *(const float4*)&ln_g[dbase + i4*4];
        float4 b = *(const float4*)&ln_b[dbase + i4*4];
        xn[i4*4+0] = (xv[i4*4+0]-mean)*rstd*g.x + b.x;
        xn[i4*4+1] = (xv[i4*4+1]-mean)*rstd*g.y + b.y;
        xn[i4*4+2] = (xv[i4*4+2]-mean)*rstd*g.z + b.z;
        xn[i4*4+3] = (xv[i4*4+3]-mean)*rstd*g.w + b.w;
    }
    float acc[32];
    #pragma unroll
    for (int c = 0; c < 32; c++) {
        const float4* wp = (const float4*)&g_WqT[c*BDIM + dbase];
        float4 w0 = __ldg(wp+0), w1 = __ldg(wp+1), w2 = __ldg(wp+2), w3 = __ldg(wp+3);
        acc[c] = xn[0]*w0.x + xn[1]*w0.y + xn[2]*w0.z + xn[3]*w0.w
               + xn[4]*w1.x + xn[5]*w1.y + xn[6]*w1.z + xn[7]*w1.w
               + xn[8]*w2.x + xn[9]*w2.y + xn[10]*w2.z + xn[11]*w2.w
               + xn[12]*w3.x + xn[13]*w3.y + xn[14]*w3.z + xn[15]*w3.w;
    }
    #pragma unroll
    for (int c = 0; c < 32; c++) red[w][c][lane] = acc[c];
    __syncwarp();
    float t = 0.f;
    #pragma unroll
    for (int j = 0; j < 32; j++) t += red[w][lane][j];
    float a = 1.f / (1.f + expf(-(t - LOGS)));
    int b = row >> 11, s = row & (SLEN-1);
    int h = lane & 15, n = lane >> 4;
    attn_out[(((size_t)b*16 + h)*2 + n)*SLEN + s] = a;
}

// ---------------- attn scalar sums: A = sum a,  Mw = sum a*rstd*mean ----------------
__global__ void k_attnsums(const float* __restrict__ attn) {
    int b = blockIdx.x, c = blockIdx.y;
    int n = c >> 4, h = c & 15;
    const float* ap = &attn[(((size_t)b*16 + h)*2 + n)*SLEN];
    __shared__ float s1[256], s2[256];
    float a1 = 0.f, a2 = 0.f;
    for (int s = threadIdx.x; s < SLEN; s += 256) {
        float a = ap[s];
        float m = g_stats[(b*SLEN + s)*2];
        float r = g_stats[(b*SLEN + s)*2 + 1];
        a1 += a;
        a2 += a*r*m;
    }
    s1[threadIdx.x] = a1; s2[threadIdx.x] = a2;
    __syncthreads();
    for (int off = 128; off; off >>= 1) {
        if (threadIdx.x < off) { s1[threadIdx.x] += s1[threadIdx.x+off]; s2[threadIdx.x] += s2[threadIdx.x+off]; }
        __syncthreads();
    }
    if (threadIdx.x == 0) { g_A[b*NC + c] = s1[0]; g_Mw[b*NC + c] = s2[0]; }
}

// ---------------- pooling partials: P[b][sc][c][d] = sum_s (a*rstd)*x2 ----------------
__global__ __launch_bounds__(128) void k_pool(const float* __restrict__ attn) {
    int b  = blockIdx.z;
    int s0 = blockIdx.y * 512;
    int d  = blockIdx.x * 128 + threadIdx.x;
    __shared__ float sw[32][128];
    float acc[32];
    #pragma unroll
    for (int c = 0; c < 32; c++) acc[c] = 0.f;

    for (int stile = 0; stile < 512; stile += 128) {
        int s = s0 + stile + threadIdx.x;
        float r = g_stats[(b*SLEN + s)*2 + 1];
        __syncthreads();
        #pragma unroll
        for (int c = 0; c < 32; c++) {
            int n = c >> 4, h = c & 15;
            sw[c][threadIdx.x] = attn[(((size_t)b*16 + h)*2 + n)*SLEN + s] * r;
        }
        __syncthreads();
        const float* xp = &g_x2[((size_t)b*SLEN + s0 + stile)*BDIM + d];
        #pragma unroll 4
        for (int si = 0; si < 128; si += 4) {
            float x0 = xp[(size_t)(si+0)*BDIM];
            float x1 = xp[(size_t)(si+1)*BDIM];
            float x2v = xp[(size_t)(si+2)*BDIM];
            float x3 = xp[(size_t)(si+3)*BDIM];
            #pragma unroll
            for (int c = 0; c < 32; c++) {
                float4 wv = *(float4*)&sw[c][si];
                acc[c] += wv.x*x0 + wv.y*x1 + wv.z*x2v + wv.w*x3;
            }
        }
    }
    #pragma unroll
    for (int c = 0; c < 32; c++)
        g_Ppart[(((size_t)b*4 + blockIdx.y)*NC + c)*BDIM + d] = acc[c];
}

// ---------------- combine partials -> pooled_xn ----------------
__global__ void k_pooled(const float* __restrict__ ln_g, const float* __restrict__ ln_b) {
    int c = blockIdx.x, b = blockIdx.y, d = threadIdx.x;
    float p = 0.f;
    #pragma unroll
    for (int sc = 0; sc < 4; sc++)
        p += g_Ppart[(((size_t)b*4 + sc)*NC + c)*BDIM + d];
    float val = ln_g[d]*(p - g_Mw[b*NC + c]) + ln_b[d]*g_A[b*NC + c];
    g_pooled[((size_t)b*NC + c)*BDIM + d] = val;
}

// ---------------- o_head = pooled @ Wv (per-head) ----------------
__global__ void k_ohead(const float* __restrict__ Wkv) {
    int b = blockIdx.x, n = blockIdx.y, dp = threadIdx.x;
    int h = dp >> 5;
    const float* pp = &g_pooled[((size_t)b*NC + n*16 + h)*BDIM];
    float acc = 0.f;
    #pragma unroll 4
    for (int d = 0; d < BDIM; d++)
        acc += pp[d] * Wkv[(size_t)d*1024 + 512 + dp];
    g_ohead[(b*2 + n)*BDIM + dp] = acc;
}

// ---------------- o = o_head @ Wproj + bproj ----------------
__global__ void k_oproj(const float* __restrict__ Wproj, const float* __restrict__ bproj) {
    __shared__ float sv[BDIM];
    int r = blockIdx.x, dp = threadIdx.x;
    sv[dp] = g_ohead[r*BDIM + dp];
    __syncthreads();
    float acc = 0.f;
    #pragma unroll 4
    for (int d = 0; d < BDIM; d++)
        acc += sv[d] * Wproj[(size_t)d*BDIM + dp];
    g_o[r*BDIM + dp] = acc + bproj[dp];
}

// ---------------- classifier head -> logits ----------------
__global__ void k_head(const float* __restrict__ g2, const float* __restrict__ b2,
                       const float* __restrict__ Wc1, const float* __restrict__ bc1,
                       const float* __restrict__ Wc2, const float* __restrict__ bc2,
                       float* __restrict__ out) {
    __shared__ float sx[BDIM];
    __shared__ float sr[BDIM];
    int r = blockIdx.x, j = threadIdx.x;
    float v = g_o[r*BDIM + j];
    sr[j] = v; __syncthreads();
    for (int off = 256; off; off >>= 1) {
        if (j < off) sr[j] += sr[j + off];
        __syncthreads();
    }
    float mean = sr[0] * (1.f/512.f);
    __syncthreads();
    float dv = v - mean;
    sr[j] = dv*dv; __syncthreads();
    for (int off = 256; off; off >>= 1) {
        if (j < off) sr[j] += sr[j + off];
        __syncthreads();
    }
    float rstd = rsqrtf(sr[0]*(1.f/512.f) + 1e-5f);
    __syncthreads();
    sx[j] = dv*rstd*g2[j] + b2[j];
    __syncthreads();
    float hj = bc1[j];
    #pragma unroll 4
    for (int d = 0; d < BDIM; d++)
        hj += sx[d] * Wc1[(size_t)d*BDIM + j];
    hj = fmaxf(hj, 0.f);
    sr[j] = hj * Wc2[j];
    __syncthreads();
    for (int off = 256; off; off >>= 1) {
        if (j < off) sr[j] += sr[j + off];
        __syncthreads();
    }
    if (j == 0) out[r] = sr[0] + bc2[0];
}

// ---------------- launch ----------------
extern "C" void kernel_launch(void* const* d_in, const int* in_sizes, int n_in,
                              void* d_out, int out_size) {
    const float* x      = (const float*)d_in[0];
    const float* wave1  = (const float*)d_in[1];
    const float* wave2  = (const float*)d_in[2];
    const float* wave3  = (const float*)d_in[3];
    const float* Wp1    = (const float*)d_in[4];
    const float* bp1    = (const float*)d_in[5];
    const float* cls    = (const float*)d_in[6];
    const float* ln1_g  = (const float*)d_in[7];
    const float* ln1_b  = (const float*)d_in[8];
    const float* Wq     = (const float*)d_in[9];
    const float* Wkv    = (const float*)d_in[10];
    const float* Wproj  = (const float*)d_in[11];
    const float* bproj  = (const float*)d_in[12];
    const float* ln2_g  = (const float*)d_in[13];
    const float* ln2_b  = (const float*)d_in[14];
    const float* Wc1    = (const float*)d_in[15];
    const float* bc1    = (const float*)d_in[16];
    const float* Wc2    = (const float*)d_in[17];
    const float* bc2    = (const float*)d_in[18];

    float* out  = (float*)d_out;
    float* attn = out + BATCH*2;   // logits [32,2] first, then attn [32,16,2,2048]

    k_qfull<<<2, BDIM>>>(cls, Wq);
    k_weff<<<NC, BDIM>>>(Wkv);
    k_wavelet<<<KS, BDIM>>>(wave1, wave2, wave3);
    k_conv<<<NROWS, BDIM>>>(x);
    {
        dim3 g(4, NROWS/128);
        k_gemm_wp1<<<g, 256>>>(x, Wp1, bp1);
    }
    k_scores<<<NROWS/8, 256>>>(ln1_g, ln1_b, attn);
    {
        dim3 g(BATCH, NC);
        k_attnsums<<<g, 256>>>(attn);
    }
    {
        dim3 g(4, 4, BATCH);
        k_pool<<<g, 128>>>(attn);
    }
    {
        dim3 g(NC, BATCH);
        k_pooled<<<g, BDIM>>>(ln1_g, ln1_b);
    }
    {
        dim3 g(BATCH, 2);
        k_ohead<<<g, BDIM>>>(Wkv);
    }
    k_oproj<<<BATCH*2, BDIM>>>(Wproj, bproj);
    k_head<<<BATCH*2, BDIM>>>(ln2_g, ln2_b, Wc1, bc1, Wc2, bc2, out);
}

// round 2
// speedup vs baseline: 1.6979x; 1.6979x over previous
#include <cuda_runtime.h>
#include <math.h>
#include <stdint.h>

#define BDIM 512
#define SLEN 2048
#define BATCH 32
#define NROWS (BATCH*SLEN)
#define KS 19
#define NC 32                    // NCLS * H
#define LOGS 7.6246189861594f    // log(2048)

// ---------------- scratch (static device globals; no allocs) ----------------
__device__ float g_Wc[BDIM*KS];                    // combined wavelet kernel [d][t]
__device__ float g_qfull[2*BDIM];                  // q rows [n][512]
__device__ float g_WqT[NC*BDIM];                   // WqEff transposed [c][d], scale folded
__device__ float g_pos[(size_t)NROWS*BDIM];        // conv output
__device__ float g_x2[(size_t)NROWS*BDIM];         // x + pos@Wp1 + bp1
__device__ float g_stats[NROWS*2];                 // per-row mean, rstd
__device__ float g_Ppart[BATCH*4*NC*BDIM];         // pooling partials [b][schunk][c][d]
__device__ float g_A[BATCH*NC];                    // sum attn
__device__ float g_Mw[BATCH*NC];                   // sum attn*rstd*mean
__device__ float g_pooled[BATCH*NC*BDIM];          // pooled xn [b][c][d]
__device__ float g_ohead[BATCH*2*BDIM];            // o before Wproj
__device__ float g_o[BATCH*2*BDIM];                // o after Wproj

// ---------------- tiny precompute kernels ----------------
__global__ void k_qfull(const float* __restrict__ cls, const float* __restrict__ Wq) {
    int n = blockIdx.x, j = threadIdx.x;
    float acc = 0.f;
    #pragma unroll 8
    for (int d = 0; d < BDIM; d++) acc += cls[n*BDIM + d] * Wq[(size_t)d*BDIM + j];
    g_qfull[n*BDIM + j] = acc;
}

__global__ void k_weff(const float* __restrict__ Wkv) {
    int c = blockIdx.x, d = threadIdx.x;     // c = n*16 + h
    int n = c >> 4, h = c & 15;
    float acc = 0.f;
    #pragma unroll
    for (int hd = 0; hd < 32; hd++)
        acc += Wkv[(size_t)d*1024 + h*32 + hd] * g_qfull[n*BDIM + h*32 + hd];
    g_WqT[c*BDIM + d] = acc * 0.17677669529663689f;  // * HD^-0.5
}

__global__ void k_wavelet(const float* __restrict__ w1, const float* __restrict__ w2,
                          const float* __restrict__ w3) {
    int d = threadIdx.x, t = blockIdx.x;
    const float C = 0.8673250705840776f;     // 2 / (sqrt(3) * pi^0.25)
    float xs = (float)(t - 9);
    const float* ws[3] = {w1, w2, w3};
    float sum = 0.f;
    #pragma unroll
    for (int i = 0; i < 3; i++) {
        float scale = ws[i][d];
        float shift = ws[i][BDIM + d];
        float u = (xs - shift) / scale;
        sum += C * (1.f - u*u) * expf(-0.5f*u*u) * rsqrtf(fabsf(scale));
    }
    g_Wc[d*KS + t] = sum;
}

// ---------------- depthwise conv: smem-tiled, register accumulators ----------------
// block: 64 s-positions x 128 d-cols; 512 threads, 4 s-groups of 16 outputs/thread
#define CTS 64
#define CDC 128
__global__ __launch_bounds__(512) void k_conv(const float* __restrict__ x) {
    __shared__ float tile[CTS + 18][CDC];
    int b  = blockIdx.z;
    int s0 = blockIdx.y * CTS;
    int d0 = blockIdx.x * CDC;
    int tid = threadIdx.x;

    // stage x tile rows s0-9 .. s0+63+9 (82 rows x 128 d), zero-padded
    const int NV = (CTS + 18) * (CDC / 4);   // 2624 float4
    for (int i = tid; i < NV; i += 512) {
        int r = i / (CDC/4), c4 = i % (CDC/4);
        int s = s0 - 9 + r;
        float4 v = make_float4(0.f, 0.f, 0.f, 0.f);
        if (s >= 0 && s < SLEN)
            v = *(const float4*)&x[((size_t)b*SLEN + s)*BDIM + d0 + c4*4];
        *(float4*)&tile[r][c4*4] = v;
    }
    __syncthreads();

    int dL = tid & (CDC - 1);
    int g  = tid >> 7;                       // 0..3
    float coef[KS];
    #pragma unroll
    for (int t = 0; t < KS; t++) coef[t] = g_Wc[(d0 + dL)*KS + t];

    float acc[16];
    #pragma unroll
    for (int i = 0; i < 16; i++) acc[i] = 0.f;

    #pragma unroll
    for (int j = 0; j < 34; j++) {           // inputs covering this group's 16 outputs
        float v = tile[g*16 + j][dL];
        #pragma unroll
        for (int t = 0; t < KS; t++) {
            int s = j - t;
            if (s >= 0 && s < 16) acc[s] += v * coef[t];
        }
    }
    size_t base = ((size_t)b*SLEN + s0 + g*16)*BDIM + d0 + dL;
    #pragma unroll
    for (int i = 0; i < 16; i++)
        g_pos[base + (size_t)i*BDIM] = acc[i];
}

// ---------------- x2 = x + pos @ Wp1 + bp1  (tf32 mma.sync, 128x128x32) ----------------
__device__ __forceinline__ uint32_t f2tf32(float f) {
    uint32_t u;
    asm("cvt.rna.tf32.f32 %0, %1;" : "=r"(u) : "f"(f));
    return u;
}

#define GBM 128
#define GBN 128
#define GBK 32
__global__ __launch_bounds__(256) void k_gemm_wp1(const float* __restrict__ x,
                                                  const float* __restrict__ Wp1,
                                                  const float* __restrict__ bp1) {
    __shared__ float As[GBM][GBK + 4];   // [m][k], stride 36 floats
    __shared__ float Bs[GBK][GBN + 8];   // [k][n], stride 136 floats
    int tid  = threadIdx.x;
    int m0   = blockIdx.y * GBM;
    int n0   = blockIdx.x * GBN;
    int warp = tid >> 5, lane = tid & 31;
    int wm   = (warp & 1) * 64;          // 2 warps along m
    int wn   = (warp >> 1) * 32;         // 4 warps along n
    int gid  = lane >> 2, tig = lane & 3;

    float acc[4][4][4];
    #pragma unroll
    for (int i = 0; i < 4; i++)
        #pragma unroll
        for (int j = 0; j < 4; j++)
            #pragma unroll
            for (int r = 0; r < 4; r++) acc[i][j][r] = 0.f;

    int ar = tid >> 3, ac = (tid & 7) * 4;    // A: 32 rows/pass, 8 float4/row
    int br = tid >> 6, bc = (tid & 63) * 4;   // B: 4 rows/pass? no: 128 cols = 32 f4
    // B: 32 float4 per row -> 8 rows per pass of 256 threads
    int brr = tid >> 5, bcc = (tid & 31) * 4;

    const float* pA = &g_pos[(size_t)m0*BDIM];
    (void)br; (void)bc;

    for (int k0 = 0; k0 < BDIM; k0 += GBK) {
        #pragma unroll
        for (int p = 0; p < 4; p++) {
            int r = ar + p*32;
            float4 v = *(const float4*)&pA[(size_t)r*BDIM + k0 + ac];
            float4 t;
            t.x = __uint_as_float(f2tf32(v.x));
            t.y = __uint_as_float(f2tf32(v.y));
            t.z = __uint_as_float(f2tf32(v.z));
            t.w = __uint_as_float(f2tf32(v.w));
            *(float4*)&As[r][ac] = t;
        }
        #pragma unroll
        for (int p = 0; p < 4; p++) {
            int r = brr + p*8;
            float4 v = *(const float4*)&Wp1[(size_t)(k0 + r)*BDIM + n0 + bcc];
            float4 t;
            t.x = __uint_as_float(f2tf32(v.x));
            t.y = __uint_as_float(f2tf32(v.y));
            t.z = __uint_as_float(f2tf32(v.z));
            t.w = __uint_as_float(f2tf32(v.w));
            *(float4*)&Bs[r][bcc] = t;
        }
        __syncthreads();
        #pragma unroll
        for (int ks = 0; ks < 4; ks++) {
            int kb = ks * 8;
            uint32_t a[4][4], bf[4][2];
            #pragma unroll
            for (int mt = 0; mt < 4; mt++) {
                int m = wm + mt*16;
                a[mt][0] = __float_as_uint(As[m + gid    ][kb + tig    ]);
                a[mt][1] = __float_as_uint(As[m + gid + 8][kb + tig    ]);
                a[mt][2] = __float_as_uint(As[m + gid    ][kb + tig + 4]);
                a[mt][3] = __float_as_uint(As[m + gid + 8][kb + tig + 4]);
            }
            #pragma unroll
            for (int nt = 0; nt < 4; nt++) {
                int n = wn + nt*8 + gid;
                bf[nt][0] = __float_as_uint(Bs[kb + tig    ][n]);
                bf[nt][1] = __float_as_uint(Bs[kb + tig + 4][n]);
            }
            #pragma unroll
            for (int mt = 0; mt < 4; mt++)
                #pragma unroll
                for (int nt = 0; nt < 4; nt++) {
                    asm volatile(
                        "mma.sync.aligned.m16n8k8.row.col.f32.tf32.tf32.f32 "
                        "{%0,%1,%2,%3}, {%4,%5,%6,%7}, {%8,%9}, {%0,%1,%2,%3};\n"
                        : "+f"(acc[mt][nt][0]), "+f"(acc[mt][nt][1]),
                          "+f"(acc[mt][nt][2]), "+f"(acc[mt][nt][3])
                        : "r"(a[mt][0]), "r"(a[mt][1]), "r"(a[mt][2]), "r"(a[mt][3]),
                          "r"(bf[nt][0]), "r"(bf[nt][1]));
                }
        }
        __syncthreads();
    }

    // epilogue: x2 = acc + x + bp1
    #pragma unroll
    for (int mt = 0; mt < 4; mt++) {
        int mrow = m0 + wm + mt*16;
        #pragma unroll
        for (int nt = 0; nt < 4; nt++) {
            int n = n0 + wn + nt*8 + 2*tig;
            float bx = bp1[n], by = bp1[n+1];
            {
                size_t r = (size_t)(mrow + gid);
                float2 xv = *(const float2*)&x[r*BDIM + n];
                float2 o;
                o.x = acc[mt][nt][0] + xv.x + bx;
                o.y = acc[mt][nt][1] + xv.y + by;
                *(float2*)&g_x2[r*BDIM + n] = o;
            }
            {
                size_t r = (size_t)(mrow + gid + 8);
                float2 xv = *(const float2*)&x[r*BDIM + n];
                float2 o;
                o.x = acc[mt][nt][2] + xv.x + bx;
                o.y = acc[mt][nt][3] + xv.y + by;
                *(float2*)&g_x2[r*BDIM + n] = o;
            }
        }
    }
}

// ---------------- LN stats + scores + sigmoid -> attn output ----------------
__global__ __launch_bounds__(256) void k_scores(const float* __restrict__ ln_g,
                                                const float* __restrict__ ln_b,
                                                float* __restrict__ attn_out) {
    __shared__ float red[8][32][33];
    int w    = threadIdx.x >> 5;
    int lane = threadIdx.x & 31;
    int row  = blockIdx.x*8 + w;
    int dbase = lane*16;
    const float* xr = &g_x2[(size_t)row*BDIM + dbase];

    float xv[16];
    #pragma unroll
    for (int i4 = 0; i4 < 4; i4++) {
        float4 v = *(const float4*)(xr + i4*4);
        xv[i4*4+0] = v.x; xv[i4*4+1] = v.y; xv[i4*4+2] = v.z; xv[i4*4+3] = v.w;
    }
    float sum = 0.f, sq = 0.f;
    #pragma unroll
    for (int i = 0; i < 16; i++) { sum += xv[i]; sq += xv[i]*xv[i]; }
    #pragma unroll
    for (int off = 16; off; off >>= 1) {
        sum += __shfl_xor_sync(0xffffffffu, sum, off);
        sq  += __shfl_xor_sync(0xffffffffu, sq,  off);
    }
    float mean = sum * (1.f/512.f);
    float var  = sq  * (1.f/512.f) - mean*mean;
    float rstd = rsqrtf(var + 1e-5f);
    if (lane == 0) { g_stats[row*2] = mean; g_stats[row*2+1] = rstd; }

    float xn[16];
    #pragma unroll
    for (int i4 = 0; i4 < 4; i4++) {
        float4 g = *(const float4*)&ln_g[dbase + i4*4];
        float4 b = *(const float4*)&ln_b[dbase + i4*4];
        xn[i4*4+0] = (xv[i4*4+0]-mean)*rstd*g.x + b.x;
        xn[i4*4+1] = (xv[i4*4+1]-mean)*rstd*g.y + b.y;
        xn[i4*4+2] = (xv[i4*4+2]-mean)*rstd*g.z + b.z;
        xn[i4*4+3] = (xv[i4*4+3]-mean)*rstd*g.w + b.w;
    }
    float acc[32];
    #pragma unroll
    for (int c = 0; c < 32; c++) {
        const float4* wp = (const float4*)&g_WqT[c*BDIM + dbase];
        float4 w0 = __ldg(wp+0), w1 = __ldg(wp+1), w2 = __ldg(wp+2), w3 = __ldg(wp+3);
        acc[c] = xn[0]*w0.x + xn[1]*w0.y + xn[2]*w0.z + xn[3]*w0.w
               + xn[4]*w1.x + xn[5]*w1.y + xn[6]*w1.z + xn[7]*w1.w
               + xn[8]*w2.x + xn[9]*w2.y + xn[10]*w2.z + xn[11]*w2.w
               + xn[12]*w3.x + xn[13]*w3.y + xn[14]*w3.z + xn[15]*w3.w;
    }
    #pragma unroll
    for (int c = 0; c < 32; c++) red[w][c][lane] = acc[c];
    __syncwarp();
    float t = 0.f;
    #pragma unroll
    for (int j = 0; j < 32; j++) t += red[w][lane][j];
    float a = 1.f / (1.f + expf(-(t - LOGS)));
    int b = row >> 11, s = row & (SLEN-1);
    int h = lane & 15, n = lane >> 4;
    attn_out[(((size_t)b*16 + h)*2 + n)*SLEN + s] = a;
}

// ---------------- attn scalar sums: A = sum a,  Mw = sum a*rstd*mean ----------------
__global__ void k_attnsums(const float* __restrict__ attn) {
    int b = blockIdx.x, c = blockIdx.y;
    int n = c >> 4, h = c & 15;
    const float* ap = &attn[(((size_t)b*16 + h)*2 + n)*SLEN];
    __shared__ float s1[256], s2[256];
    float a1 = 0.f, a2 = 0.f;
    for (int s = threadIdx.x; s < SLEN; s += 256) {
        float a = ap[s];
        float m = g_stats[(b*SLEN + s)*2];
        float r = g_stats[(b*SLEN + s)*2 + 1];
        a1 += a;
        a2 += a*r*m;
    }
    s1[threadIdx.x] = a1; s2[threadIdx.x] = a2;
    __syncthreads();
    for (int off = 128; off; off >>= 1) {
        if (threadIdx.x < off) { s1[threadIdx.x] += s1[threadIdx.x+off]; s2[threadIdx.x] += s2[threadIdx.x+off]; }
        __syncthreads();
    }
    if (threadIdx.x == 0) { g_A[b*NC + c] = s1[0]; g_Mw[b*NC + c] = s2[0]; }
}

// ---------------- pooling partials: P[b][sc][c][d] = sum_s (a*rstd)*x2 ----------------
__global__ __launch_bounds__(128) void k_pool(const float* __restrict__ attn) {
    int b  = blockIdx.z;
    int s0 = blockIdx.y * 512;
    int d  = blockIdx.x * 128 + threadIdx.x;
    __shared__ float sw[32][128];
    float acc[32];
    #pragma unroll
    for (int c = 0; c < 32; c++) acc[c] = 0.f;

    for (int stile = 0; stile < 512; stile += 128) {
        int s = s0 + stile + threadIdx.x;
        float r = g_stats[(b*SLEN + s)*2 + 1];
        __syncthreads();
        #pragma unroll
        for (int c = 0; c < 32; c++) {
            int n = c >> 4, h = c & 15;
            sw[c][threadIdx.x] = attn[(((size_t)b*16 + h)*2 + n)*SLEN + s] * r;
        }
        __syncthreads();
        const float* xp = &g_x2[((size_t)b*SLEN + s0 + stile)*BDIM + d];
        #pragma unroll 4
        for (int si = 0; si < 128; si += 4) {
            float x0 = xp[(size_t)(si+0)*BDIM];
            float x1 = xp[(size_t)(si+1)*BDIM];
            float x2v = xp[(size_t)(si+2)*BDIM];
            float x3 = xp[(size_t)(si+3)*BDIM];
            #pragma unroll
            for (int c = 0; c < 32; c++) {
                float4 wv = *(float4*)&sw[c][si];
                acc[c] += wv.x*x0 + wv.y*x1 + wv.z*x2v + wv.w*x3;
            }
        }
    }
    #pragma unroll
    for (int c = 0; c < 32; c++)
        g_Ppart[(((size_t)b*4 + blockIdx.y)*NC + c)*BDIM + d] = acc[c];
}

// ---------------- combine partials -> pooled_xn ----------------
__global__ void k_pooled(const float* __restrict__ ln_g, const float* __restrict__ ln_b) {
    int c = blockIdx.x, b = blockIdx.y, d = threadIdx.x;
    float p = 0.f;
    #pragma unroll
    for (int sc = 0; sc < 4; sc++)
        p += g_Ppart[(((size_t)b*4 + sc)*NC + c)*BDIM + d];
    float val = ln_g[d]*(p - g_Mw[b*NC + c]) + ln_b[d]*g_A[b*NC + c];
    g_pooled[((size_t)b*NC + c)*BDIM + d] = val;
}

// ---------------- o_head = pooled @ Wv (per-head) ----------------
__global__ void k_ohead(const float* __restrict__ Wkv) {
    int b = blockIdx.x, n = blockIdx.y, dp = threadIdx.x;
    int h = dp >> 5;
    const float* pp = &g_pooled[((size_t)b*NC + n*16 + h)*BDIM];
    float acc = 0.f;
    #pragma unroll 4
    for (int d = 0; d < BDIM; d++)
        acc += pp[d] * Wkv[(size_t)d*1024 + 512 + dp];
    g_ohead[(b*2 + n)*BDIM + dp] = acc;
}

// ---------------- o = o_head @ Wproj + bproj ----------------
__global__ void k_oproj(const float* __restrict__ Wproj, const float* __restrict__ bproj) {
    __shared__ float sv[BDIM];
    int r = blockIdx.x, dp = threadIdx.x;
    sv[dp] = g_ohead[r*BDIM + dp];
    __syncthreads();
    float acc = 0.f;
    #pragma unroll 4
    for (int d = 0; d < BDIM; d++)
        acc += sv[d] * Wproj[(size_t)d*BDIM + dp];
    g_o[r*BDIM + dp] = acc + bproj[dp];
}

// ---------------- classifier head -> logits ----------------
__global__ void k_head(const float* __restrict__ g2, const float* __restrict__ b2,
                       const float* __restrict__ Wc1, const float* __restrict__ bc1,
                       const float* __restrict__ Wc2, const float* __restrict__ bc2,
                       float* __restrict__ out) {
    __shared__ float sx[BDIM];
    __shared__ float sr[BDIM];
    int r = blockIdx.x, j = threadIdx.x;
    float v = g_o[r*BDIM + j];
    sr[j] = v; __syncthreads();
    for (int off = 256; off; off >>= 1) {
        if (j < off) sr[j] += sr[j + off];
        __syncthreads();
    }
    float mean = sr[0] * (1.f/512.f);
    __syncthreads();
    float dv = v - mean;
    sr[j] = dv*dv; __syncthreads();
    for (int off = 256; off; off >>= 1) {
        if (j < off) sr[j] += sr[j + off];
        __syncthreads();
    }
    float rstd = rsqrtf(sr[0]*(1.f/512.f) + 1e-5f);
    __syncthreads();
    sx[j] = dv*rstd*g2[j] + b2[j];
    __syncthreads();
    float hj = bc1[j];
    #pragma unroll 4
    for (int d = 0; d < BDIM; d++)
        hj += sx[d] * Wc1[(size_t)d*BDIM + j];
    hj = fmaxf(hj, 0.f);
    sr[j] = hj * Wc2[j];
    __syncthreads();
    for (int off = 256; off; off >>= 1) {
        if (j < off) sr[j] += sr[j + off];
        __syncthreads();
    }
    if (j == 0) out[r] = sr[0] + bc2[0];
}

// ---------------- launch ----------------
extern "C" void kernel_launch(void* const* d_in, const int* in_sizes, int n_in,
                              void* d_out, int out_size) {
    const float* x      = (const float*)d_in[0];
    const float* wave1  = (const float*)d_in[1];
    const float* wave2  = (const float*)d_in[2];
    const float* wave3  = (const float*)d_in[3];
    const float* Wp1    = (const float*)d_in[4];
    const float* bp1    = (const float*)d_in[5];
    const float* cls    = (const float*)d_in[6];
    const float* ln1_g  = (const float*)d_in[7];
    const float* ln1_b  = (const float*)d_in[8];
    const float* Wq     = (const float*)d_in[9];
    const float* Wkv    = (const float*)d_in[10];
    const float* Wproj  = (const float*)d_in[11];
    const float* bproj  = (const float*)d_in[12];
    const float* ln2_g  = (const float*)d_in[13];
    const float* ln2_b  = (const float*)d_in[14];
    const float* Wc1    = (const float*)d_in[15];
    const float* bc1    = (const float*)d_in[16];
    const float* Wc2    = (const float*)d_in[17];
    const float* bc2    = (const float*)d_in[18];

    float* out  = (float*)d_out;
    float* attn = out + BATCH*2;   // logits [32,2] first, then attn [32,16,2,2048]

    k_qfull<<<2, BDIM>>>(cls, Wq);
    k_weff<<<NC, BDIM>>>(Wkv);
    k_wavelet<<<KS, BDIM>>>(wave1, wave2, wave3);
    {
        dim3 g(BDIM/CDC, SLEN/CTS, BATCH);   // (4, 32, 32)
        k_conv<<<g, 512>>>(x);
    }
    {
        dim3 g(BDIM/GBN, NROWS/GBM);         // (4, 512)
        k_gemm_wp1<<<g, 256>>>(x, Wp1, bp1);
    }
    k_scores<<<NROWS/8, 256>>>(ln1_g, ln1_b, attn);
    {
        dim3 g(BATCH, NC);
        k_attnsums<<<g, 256>>>(attn);
    }
    {
        dim3 g(4, 4, BATCH);
        k_pool<<<g, 128>>>(attn);
    }
    {
        dim3 g(NC, BATCH);
        k_pooled<<<g, BDIM>>>(ln1_g, ln1_b);
    }
    {
        dim3 g(BATCH, 2);
        k_ohead<<<g, BDIM>>>(Wkv);
    }
    k_oproj<<<BATCH*2, BDIM>>>(Wproj, bproj);
    k_head<<<BATCH*2, BDIM>>>(ln2_g, ln2_b, Wc1, bc1, Wc2, bc2, out);
}

// round 4
// speedup vs baseline: 1.7537x; 1.0328x over previous
#include <cuda_runtime.h>
#include <math.h>
#include <stdint.h>

#define BDIM 512
#define SLEN 2048
#define BATCH 32
#define NROWS (BATCH*SLEN)
#define KS 19
#define NC 32                    // NCLS * H
#define LOGS 7.6246189861594f    // log(2048)

// ---------------- scratch (static device globals; no allocs) ----------------
__device__ float g_Wc[BDIM*KS];                    // combined wavelet kernel [d][t]
__device__ float g_qfull[2*BDIM];                  // q rows [n][512]
__device__ float g_WqT[NC*BDIM];                   // WqEff transposed [c][d], scale folded
__device__ float g_Wp1r[BDIM*BDIM];                // Wp1 [k][n], tf32-rounded
__device__ float g_pos[(size_t)NROWS*BDIM];        // conv output (tf32-rounded)
__device__ float g_x2[(size_t)NROWS*BDIM];         // x + pos@Wp1 + bp1
__device__ float g_stats[NROWS*2];                 // per-row mean, rstd
__device__ float g_Ppart[BATCH*4*NC*BDIM];         // pooling partials [b][schunk][c][d]
__device__ float g_A[BATCH*NC];                    // sum attn
__device__ float g_Mw[BATCH*NC];                   // sum attn*rstd*mean
__device__ float g_pooled[BATCH*NC*BDIM];          // pooled xn [b][c][d]
__device__ float g_ohead[BATCH*2*BDIM];            // o before Wproj
__device__ float g_o[BATCH*2*BDIM];                // o after Wproj

// ---------------- helpers ----------------
__device__ __forceinline__ uint32_t f2tf32(float f) {
    uint32_t u;
    asm("cvt.rna.tf32.f32 %0, %1;" : "=r"(u) : "f"(f));
    return u;
}
__device__ __forceinline__ uint32_t s2u(const void* p) {
    uint32_t a;
    asm("{ .reg .u64 t; cvta.to.shared.u64 t, %1; cvt.u32.u64 %0, t; }" : "=r"(a) : "l"(p));
    return a;
}

// ---------------- tiny precompute kernels ----------------
__global__ void k_qfull(const float* __restrict__ cls, const float* __restrict__ Wq) {
    int n = blockIdx.x, j = threadIdx.x;
    float acc = 0.f;
    #pragma unroll 8
    for (int d = 0; d < BDIM; d++) acc += cls[n*BDIM + d] * Wq[(size_t)d*BDIM + j];
    g_qfull[n*BDIM + j] = acc;
}

__global__ void k_weff(const float* __restrict__ Wkv) {
    int c = blockIdx.x, d = threadIdx.x;     // c = n*16 + h
    int n = c >> 4, h = c & 15;
    float acc = 0.f;
    #pragma unroll
    for (int hd = 0; hd < 32; hd++)
        acc += Wkv[(size_t)d*1024 + h*32 + hd] * g_qfull[n*BDIM + h*32 + hd];
    g_WqT[c*BDIM + d] = acc * 0.17677669529663689f;  // * HD^-0.5
}

__global__ void k_wavelet(const float* __restrict__ w1, const float* __restrict__ w2,
                          const float* __restrict__ w3) {
    int d = threadIdx.x, t = blockIdx.x;
    const float C = 0.8673250705840776f;     // 2 / (sqrt(3) * pi^0.25)
    float xs = (float)(t - 9);
    const float* ws[3] = {w1, w2, w3};
    float sum = 0.f;
    #pragma unroll
    for (int i = 0; i < 3; i++) {
        float scale = ws[i][d];
        float shift = ws[i][BDIM + d];
        float u = (xs - shift) / scale;
        sum += C * (1.f - u*u) * expf(-0.5f*u*u) * rsqrtf(fabsf(scale));
    }
    g_Wc[d*KS + t] = sum;
}

// tf32-round Wp1 in place layout [k][n]
__global__ void k_wp1r(const float* __restrict__ Wp1) {
    int i = blockIdx.x * 512 + threadIdx.x;
    g_Wp1r[i] = __uint_as_float(f2tf32(Wp1[i]));
}

// ---------------- depthwise conv: smem-tiled, register accumulators ----------------
#define CTS 64
#define CDC 128
__global__ __launch_bounds__(512) void k_conv(const float* __restrict__ x) {
    __shared__ float tile[CTS + 18][CDC];
    int b  = blockIdx.z;
    int s0 = blockIdx.y * CTS;
    int d0 = blockIdx.x * CDC;
    int tid = threadIdx.x;

    const int NV = (CTS + 18) * (CDC / 4);
    for (int i = tid; i < NV; i += 512) {
        int r = i / (CDC/4), c4 = i % (CDC/4);
        int s = s0 - 9 + r;
        float4 v = make_float4(0.f, 0.f, 0.f, 0.f);
        if (s >= 0 && s < SLEN)
            v = *(const float4*)&x[((size_t)b*SLEN + s)*BDIM + d0 + c4*4];
        *(float4*)&tile[r][c4*4] = v;
    }
    __syncthreads();

    int dL = tid & (CDC - 1);
    int g  = tid >> 7;
    float coef[KS];
    #pragma unroll
    for (int t = 0; t < KS; t++) coef[t] = g_Wc[(d0 + dL)*KS + t];

    float acc[16];
    #pragma unroll
    for (int i = 0; i < 16; i++) acc[i] = 0.f;

    #pragma unroll
    for (int j = 0; j < 34; j++) {
        float v = tile[g*16 + j][dL];
        #pragma unroll
        for (int t = 0; t < KS; t++) {
            int s = j - t;
            if (s >= 0 && s < 16) acc[s] += v * coef[t];
        }
    }
    size_t base = ((size_t)b*SLEN + s0 + g*16)*BDIM + d0 + dL;
    #pragma unroll
    for (int i = 0; i < 16; i++)
        g_pos[base + (size_t)i*BDIM] = __uint_as_float(f2tf32(acc[i]));  // pre-round for MMA
}

// ---------------- x2 = x + pos @ Wp1 + bp1 (tf32 mma.sync, cp.async 3-stage) ----------------
#define GM 128
#define GN 256
#define KCH 32
#define NCHUNK 16
#define AST 36                   // A row stride (floats): 144B, 16B-aligned
#define BST 264                  // B row stride (floats): 1056B, 16B-aligned
#define STG_FL (GM*AST + KCH*BST)          // 13056 floats per stage
#define SM_GEMM (3*STG_FL*4)               // 156672 bytes

__global__ __launch_bounds__(256) void k_gemm(const float* __restrict__ x,
                                              const float* __restrict__ bp1) {
    extern __shared__ float sm[];
    uint32_t sb = s2u(sm);
    int tid  = threadIdx.x;
    int m0   = blockIdx.y * GM;
    int n0   = blockIdx.x * GN;
    int warp = tid >> 5, lane = tid & 31;
    int wm   = (warp & 1) * 64;          // 2 warps along m
    int wn   = (warp >> 1) * 64;         // 4 warps along n (64 each)
    int gid  = lane >> 2, tig = lane & 3;

    float acc[4][8][4];
    #pragma unroll
    for (int i = 0; i < 4; i++)
        #pragma unroll
        for (int j = 0; j < 8; j++)
            #pragma unroll
            for (int r = 0; r < 4; r++) acc[i][j][r] = 0.f;

    auto load_chunk = [&](int ch, int st) {
        uint32_t ab = sb + (uint32_t)(st * STG_FL) * 4u;
        uint32_t bb = ab + GM*AST*4u;
        const float* As = g_pos + (size_t)m0 * BDIM + ch * KCH;
        #pragma unroll
        for (int it = 0; it < 4; it++) {            // A: 128 rows x 8 x 16B
            int idx = tid + it * 256;
            int r = idx >> 3, c = idx & 7;
            uint32_t dst = ab + (uint32_t)(r*AST + c*4) * 4u;
            const float* src = As + (size_t)r * BDIM + c * 4;
            asm volatile("cp.async.cg.shared.global [%0], [%1], 16;" :: "r"(dst), "l"(src));
        }
        const float* Bs = g_Wp1r + (size_t)(ch * KCH) * BDIM + n0;
        #pragma unroll
        for (int it = 0; it < 8; it++) {            // B: 32 rows x 64 x 16B
            int idx = tid + it * 256;
            int r = idx >> 6, c = idx & 63;
            uint32_t dst = bb + (uint32_t)(r*BST + c*4) * 4u;
            const float* src = Bs + (size_t)r * BDIM + c * 4;
            asm volatile("cp.async.cg.shared.global [%0], [%1], 16;" :: "r"(dst), "l"(src));
        }
        asm volatile("cp.async.commit_group;" ::: "memory");
    };

    load_chunk(0, 0);
    load_chunk(1, 1);
    load_chunk(2, 2);

    for (int i = 0; i < NCHUNK; i++) {
        int st = i % 3;
        if (i <= NCHUNK - 3)      asm volatile("cp.async.wait_group 2;" ::: "memory");
        else if (i == NCHUNK - 2) asm volatile("cp.async.wait_group 1;" ::: "memory");
        else                      asm volatile("cp.async.wait_group 0;" ::: "memory");
        __syncthreads();

        const float* Asm = sm + st * STG_FL;
        const float* Bsm = Asm + GM*AST;
        #pragma unroll
        for (int ks = 0; ks < 4; ks++) {
            int kb = ks * 8;
            uint32_t a[4][4], bf[8][2];
            #pragma unroll
            for (int mt = 0; mt < 4; mt++) {
                int m = wm + mt*16 + gid;
                a[mt][0] = __float_as_uint(Asm[(m    )*AST + kb + tig    ]);
                a[mt][1] = __float_as_uint(Asm[(m + 8)*AST + kb + tig    ]);
                a[mt][2] = __float_as_uint(Asm[(m    )*AST + kb + tig + 4]);
                a[mt][3] = __float_as_uint(Asm[(m + 8)*AST + kb + tig + 4]);
            }
            #pragma unroll
            for (int nt = 0; nt < 8; nt++) {
                int n = wn + nt*8 + gid;
                bf[nt][0] = __float_as_uint(Bsm[(kb + tig    )*BST + n]);
                bf[nt][1] = __float_as_uint(Bsm[(kb + tig + 4)*BST + n]);
            }
            #pragma unroll
            for (int mt = 0; mt < 4; mt++)
                #pragma unroll
                for (int nt = 0; nt < 8; nt++) {
                    asm volatile(
                        "mma.sync.aligned.m16n8k8.row.col.f32.tf32.tf32.f32 "
                        "{%0,%1,%2,%3}, {%4,%5,%6,%7}, {%8,%9}, {%0,%1,%2,%3};\n"
                        : "+f"(acc[mt][nt][0]), "+f"(acc[mt][nt][1]),
                          "+f"(acc[mt][nt][2]), "+f"(acc[mt][nt][3])
                        : "r"(a[mt][0]), "r"(a[mt][1]), "r"(a[mt][2]), "r"(a[mt][3]),
                          "r"(bf[nt][0]), "r"(bf[nt][1]));
                }
        }
        __syncthreads();
        if (i + 3 < NCHUNK) load_chunk(i + 3, st);
    }

    // epilogue: x2 = acc + x + bp1
    #pragma unroll
    for (int mt = 0; mt < 4; mt++) {
        int mrow = m0 + wm + mt*16;
        #pragma unroll
        for (int nt = 0; nt < 8; nt++) {
            int n = n0 + wn + nt*8 + 2*tig;
            float bx = bp1[n], by = bp1[n+1];
            {
                size_t r = (size_t)(mrow + gid);
                float2 xv = *(const float2*)&x[r*BDIM + n];
                float2 o;
                o.x = acc[mt][nt][0] + xv.x + bx;
                o.y = acc[mt][nt][1] + xv.y + by;
                *(float2*)&g_x2[r*BDIM + n] = o;
            }
            {
                size_t r = (size_t)(mrow + gid + 8);
                float2 xv = *(const float2*)&x[r*BDIM + n];
                float2 o;
                o.x = acc[mt][nt][2] + xv.x + bx;
                o.y = acc[mt][nt][3] + xv.y + by;
                *(float2*)&g_x2[r*BDIM + n] = o;
            }
        }
    }
}

// ---------------- LN stats + scores + sigmoid -> attn output ----------------
__global__ __launch_bounds__(256) void k_scores(const float* __restrict__ ln_g,
                                                const float* __restrict__ ln_b,
                                                float* __restrict__ attn_out) {
    __shared__ float red[8][32][33];
    int w    = threadIdx.x >> 5;
    int lane = threadIdx.x & 31;
    int row  = blockIdx.x*8 + w;
    int dbase = lane*16;
    const float* xr = &g_x2[(size_t)row*BDIM + dbase];

    float xv[16];
    #pragma unroll
    for (int i4 = 0; i4 < 4; i4++) {
        float4 v = *(const float4*)(xr + i4*4);
        xv[i4*4+0] = v.x; xv[i4*4+1] = v.y; xv[i4*4+2] = v.z; xv[i4*4+3] = v.w;
    }
    float sum = 0.f, sq = 0.f;
    #pragma unroll
    for (int i = 0; i < 16; i++) { sum += xv[i]; sq += xv[i]*xv[i]; }
    #pragma unroll
    for (int off = 16; off; off >>= 1) {
        sum += __shfl_xor_sync(0xffffffffu, sum, off);
        sq  += __shfl_xor_sync(0xffffffffu, sq,  off);
    }
    float mean = sum * (1.f/512.f);
    float var  = sq  * (1.f/512.f) - mean*mean;
    float rstd = rsqrtf(var + 1e-5f);
    if (lane == 0) { g_stats[row*2] = mean; g_stats[row*2+1] = rstd; }

    float xn[16];
    #pragma unroll
    for (int i4 = 0; i4 < 4; i4++) {
        float4 g = *(const float4*)&ln_g[dbase + i4*4];
        float4 b = *(const float4*)&ln_b[dbase + i4*4];
        xn[i4*4+0] = (xv[i4*4+0]-mean)*rstd*g.x + b.x;
        xn[i4*4+1] = (xv[i4*4+1]-mean)*rstd*g.y + b.y;
        xn[i4*4+2] = (xv[i4*4+2]-mean)*rstd*g.z + b.z;
        xn[i4*4+3] = (xv[i4*4+3]-mean)*rstd*g.w + b.w;
    }
    float acc[32];
    #pragma unroll
    for (int c = 0; c < 32; c++) {
        const float4* wp = (const float4*)&g_WqT[c*BDIM + dbase];
        float4 w0 = __ldg(wp+0), w1 = __ldg(wp+1), w2 = __ldg(wp+2), w3 = __ldg(wp+3);
        acc[c] = xn[0]*w0.x + xn[1]*w0.y + xn[2]*w0.z + xn[3]*w0.w
               + xn[4]*w1.x + xn[5]*w1.y + xn[6]*w1.z + xn[7]*w1.w
               + xn[8]*w2.x + xn[9]*w2.y + xn[10]*w2.z + xn[11]*w2.w
               + xn[12]*w3.x + xn[13]*w3.y + xn[14]*w3.z + xn[15]*w3.w;
    }
    #pragma unroll
    for (int c = 0; c < 32; c++) red[w][c][lane] = acc[c];
    __syncwarp();
    float t = 0.f;
    #pragma unroll
    for (int j = 0; j < 32; j++) t += red[w][lane][j];
    float a = 1.f / (1.f + expf(-(t - LOGS)));
    int b = row >> 11, s = row & (SLEN-1);
    int h = lane & 15, n = lane >> 4;
    attn_out[(((size_t)b*16 + h)*2 + n)*SLEN + s] = a;
}

// ---------------- attn scalar sums ----------------
__global__ void k_attnsums(const float* __restrict__ attn) {
    int b = blockIdx.x, c = blockIdx.y;
    int n = c >> 4, h = c & 15;
    const float* ap = &attn[(((size_t)b*16 + h)*2 + n)*SLEN];
    __shared__ float s1[256], s2[256];
    float a1 = 0.f, a2 = 0.f;
    for (int s = threadIdx.x; s < SLEN; s += 256) {
        float a = ap[s];
        float m = g_stats[(b*SLEN + s)*2];
        float r = g_stats[(b*SLEN + s)*2 + 1];
        a1 += a;
        a2 += a*r*m;
    }
    s1[threadIdx.x] = a1; s2[threadIdx.x] = a2;
    __syncthreads();
    for (int off = 128; off; off >>= 1) {
        if (threadIdx.x < off) { s1[threadIdx.x] += s1[threadIdx.x+off]; s2[threadIdx.x] += s2[threadIdx.x+off]; }
        __syncthreads();
    }
    if (threadIdx.x == 0) { g_A[b*NC + c] = s1[0]; g_Mw[b*NC + c] = s2[0]; }
}

// ---------------- pooling partials ----------------
__global__ __launch_bounds__(128) void k_pool(const float* __restrict__ attn) {
    int b  = blockIdx.z;
    int s0 = blockIdx.y * 512;
    int d  = blockIdx.x * 128 + threadIdx.x;
    __shared__ float sw[32][128];
    float acc[32];
    #pragma unroll
    for (int c = 0; c < 32; c++) acc[c] = 0.f;

    for (int stile = 0; stile < 512; stile += 128) {
        int s = s0 + stile + threadIdx.x;
        float r = g_stats[(b*SLEN + s)*2 + 1];
        __syncthreads();
        #pragma unroll
        for (int c = 0; c < 32; c++) {
            int n = c >> 4, h = c & 15;
            sw[c][threadIdx.x] = attn[(((size_t)b*16 + h)*2 + n)*SLEN + s] * r;
        }
        __syncthreads();
        const float* xp = &g_x2[((size_t)b*SLEN + s0 + stile)*BDIM + d];
        #pragma unroll 4
        for (int si = 0; si < 128; si += 4) {
            float x0 = xp[(size_t)(si+0)*BDIM];
            float x1 = xp[(size_t)(si+1)*BDIM];
            float x2v = xp[(size_t)(si+2)*BDIM];
            float x3 = xp[(size_t)(si+3)*BDIM];
            #pragma unroll
            for (int c = 0; c < 32; c++) {
                float4 wv = *(float4*)&sw[c][si];
                acc[c] += wv.x*x0 + wv.y*x1 + wv.z*x2v + wv.w*x3;
            }
        }
    }
    #pragma unroll
    for (int c = 0; c < 32; c++)
        g_Ppart[(((size_t)b*4 + blockIdx.y)*NC + c)*BDIM + d] = acc[c];
}

__global__ void k_pooled(const float* __restrict__ ln_g, const float* __restrict__ ln_b) {
    int c = blockIdx.x, b = blockIdx.y, d = threadIdx.x;
    float p = 0.f;
    #pragma unroll
    for (int sc = 0; sc < 4; sc++)
        p += g_Ppart[(((size_t)b*4 + sc)*NC + c)*BDIM + d];
    float val = ln_g[d]*(p - g_Mw[b*NC + c]) + ln_b[d]*g_A[b*NC + c];
    g_pooled[((size_t)b*NC + c)*BDIM + d] = val;
}

__global__ void k_ohead(const float* __restrict__ Wkv) {
    int b = blockIdx.x, n = blockIdx.y, dp = threadIdx.x;
    int h = dp >> 5;
    const float* pp = &g_pooled[((size_t)b*NC + n*16 + h)*BDIM];
    float acc = 0.f;
    #pragma unroll 4
    for (int d = 0; d < BDIM; d++)
        acc += pp[d] * Wkv[(size_t)d*1024 + 512 + dp];
    g_ohead[(b*2 + n)*BDIM + dp] = acc;
}

__global__ void k_oproj(const float* __restrict__ Wproj, const float* __restrict__ bproj) {
    __shared__ float sv[BDIM];
    int r = blockIdx.x, dp = threadIdx.x;
    sv[dp] = g_ohead[r*BDIM + dp];
    __syncthreads();
    float acc = 0.f;
    #pragma unroll 4
    for (int d = 0; d < BDIM; d++)
        acc += sv[d] * Wproj[(size_t)d*BDIM + dp];
    g_o[r*BDIM + dp] = acc + bproj[dp];
}

__global__ void k_head(const float* __restrict__ g2, const float* __restrict__ b2,
                       const float* __restrict__ Wc1, const float* __restrict__ bc1,
                       const float* __restrict__ Wc2, const float* __restrict__ bc2,
                       float* __restrict__ out) {
    __shared__ float sx[BDIM];
    __shared__ float sr[BDIM];
    int r = blockIdx.x, j = threadIdx.x;
    float v = g_o[r*BDIM + j];
    sr[j] = v; __syncthreads();
    for (int off = 256; off; off >>= 1) {
        if (j < off) sr[j] += sr[j + off];
        __syncthreads();
    }
    float mean = sr[0] * (1.f/512.f);
    __syncthreads();
    float dv = v - mean;
    sr[j] = dv*dv; __syncthreads();
    for (int off = 256; off; off >>= 1) {
        if (j < off) sr[j] += sr[j + off];
        __syncthreads();
    }
    float rstd = rsqrtf(sr[0]*(1.f/512.f) + 1e-5f);
    __syncthreads();
    sx[j] = dv*rstd*g2[j] + b2[j];
    __syncthreads();
    float hj = bc1[j];
    #pragma unroll 4
    for (int d = 0; d < BDIM; d++)
        hj += sx[d] * Wc1[(size_t)d*BDIM + j];
    hj = fmaxf(hj, 0.f);
    sr[j] = hj * Wc2[j];
    __syncthreads();
    for (int off = 256; off; off >>= 1) {
        if (j < off) sr[j] += sr[j + off];
        __syncthreads();
    }
    if (j == 0) out[r] = sr[0] + bc2[0];
}

// ---------------- launch ----------------
extern "C" void kernel_launch(void* const* d_in, const int* in_sizes, int n_in,
                              void* d_out, int out_size) {
    const float* x      = (const float*)d_in[0];
    const float* wave1  = (const float*)d_in[1];
    const float* wave2  = (const float*)d_in[2];
    const float* wave3  = (const float*)d_in[3];
    const float* Wp1    = (const float*)d_in[4];
    const float* bp1    = (const float*)d_in[5];
    const float* cls    = (const float*)d_in[6];
    const float* ln1_g  = (const float*)d_in[7];
    const float* ln1_b  = (const float*)d_in[8];
    const float* Wq     = (const float*)d_in[9];
    const float* Wkv    = (const float*)d_in[10];
    const float* Wproj  = (const float*)d_in[11];
    const float* bproj  = (const float*)d_in[12];
    const float* ln2_g  = (const float*)d_in[13];
    const float* ln2_b  = (const float*)d_in[14];
    const float* Wc1    = (const float*)d_in[15];
    const float* bc1    = (const float*)d_in[16];
    const float* Wc2    = (const float*)d_in[17];
    const float* bc2    = (const float*)d_in[18];

    float* out  = (float*)d_out;
    float* attn = out + BATCH*2;   // logits [32,2] first, then attn [32,16,2,2048]

    static int smem_set = 0;
    if (!smem_set) {
        cudaFuncSetAttribute(k_gemm, cudaFuncAttributeMaxDynamicSharedMemorySize, SM_GEMM);
        smem_set = 1;
    }

    k_qfull<<<2, BDIM>>>(cls, Wq);
    k_weff<<<NC, BDIM>>>(Wkv);
    k_wavelet<<<KS, BDIM>>>(wave1, wave2, wave3);
    k_wp1r<<<BDIM, 512>>>(Wp1);
    {
        dim3 g(BDIM/CDC, SLEN/CTS, BATCH);   // (4, 32, 32)
        k_conv<<<g, 512>>>(x);
    }
    {
        dim3 g(BDIM/GN, NROWS/GM);           // (2, 512)
        k_gemm<<<g, 256, SM_GEMM>>>(x, bp1);
    }
    k_scores<<<NROWS/8, 256>>>(ln1_g, ln1_b, attn);
    {
        dim3 g(BATCH, NC);
        k_attnsums<<<g, 256>>>(attn);
    }
    {
        dim3 g(4, 4, BATCH);
        k_pool<<<g, 128>>>(attn);
    }
    {
        dim3 g(NC, BATCH);
        k_pooled<<<g, BDIM>>>(ln1_g, ln1_b);
    }
    {
        dim3 g(BATCH, 2);
        k_ohead<<<g, BDIM>>>(Wkv);
    }
    k_oproj<<<BATCH*2, BDIM>>>(Wproj, bproj);
    k_head<<<BATCH*2, BDIM>>>(ln2_g, ln2_b, Wc1, bc1, Wc2, bc2, out);
}

// round 5
// speedup vs baseline: 1.8769x; 1.0703x over previous
#include <cuda_runtime.h>
#include <cuda_fp16.h>
#include <math.h>
#include <stdint.h>

#define BDIM 512
#define SLEN 2048
#define BATCH 32
#define NROWS (BATCH*SLEN)
#define KS 19
#define NC 32                    // NCLS * H
#define LOGS 7.6246189861594f    // log(2048)

// ---------------- scratch (static device globals; no allocs) ----------------
__device__ float  g_Wc[BDIM*KS];                   // combined wavelet kernel [d][t]
__device__ float  g_qfull[2*BDIM];                 // q rows [n][512]
__device__ float  g_WqT[NC*BDIM];                  // WqEff transposed [c][d], scale folded
__device__ __half g_Wp1h[BDIM*BDIM];               // Wp1 transposed [n][k], fp16
__device__ __half g_posh[(size_t)NROWS*BDIM];      // conv output, fp16
__device__ float  g_x2[(size_t)NROWS*BDIM];        // x + pos@Wp1 + bp1
__device__ float  g_stats[NROWS*2];                // per-row mean, rstd
__device__ float  g_Ppart[BATCH*4*NC*BDIM];        // pooling partials
__device__ float  g_A[BATCH*NC];                   // sum attn
__device__ float  g_Mw[BATCH*NC];                  // sum attn*rstd*mean
__device__ float  g_pooled[BATCH*NC*BDIM];         // pooled xn [b][c][d]
__device__ float  g_ohead[BATCH*2*BDIM];           // o before Wproj
__device__ float  g_o[BATCH*2*BDIM];               // o after Wproj

// ---------------- helpers ----------------
__device__ __forceinline__ uint32_t s2u(const void* p) {
    uint32_t a;
    asm("{ .reg .u64 t; cvta.to.shared.u64 t, %1; cvt.u32.u64 %0, t; }" : "=r"(a) : "l"(p));
    return a;
}

// ---------------- tiny precompute kernels ----------------
__global__ void k_qfull(const float* __restrict__ cls, const float* __restrict__ Wq) {
    int n = blockIdx.x, j = threadIdx.x;
    float acc = 0.f;
    #pragma unroll 8
    for (int d = 0; d < BDIM; d++) acc += cls[n*BDIM + d] * Wq[(size_t)d*BDIM + j];
    g_qfull[n*BDIM + j] = acc;
}

__global__ void k_weff(const float* __restrict__ Wkv) {
    int c = blockIdx.x, d = threadIdx.x;     // c = n*16 + h
    int n = c >> 4, h = c & 15;
    float acc = 0.f;
    #pragma unroll
    for (int hd = 0; hd < 32; hd++)
        acc += Wkv[(size_t)d*1024 + h*32 + hd] * g_qfull[n*BDIM + h*32 + hd];
    g_WqT[c*BDIM + d] = acc * 0.17677669529663689f;  // * HD^-0.5
}

__global__ void k_wavelet(const float* __restrict__ w1, const float* __restrict__ w2,
                          const float* __restrict__ w3) {
    int d = threadIdx.x, t = blockIdx.x;
    const float C = 0.8673250705840776f;     // 2 / (sqrt(3) * pi^0.25)
    float xs = (float)(t - 9);
    const float* ws[3] = {w1, w2, w3};
    float sum = 0.f;
    #pragma unroll
    for (int i = 0; i < 3; i++) {
        float scale = ws[i][d];
        float shift = ws[i][BDIM + d];
        float u = (xs - shift) / scale;
        sum += C * (1.f - u*u) * expf(-0.5f*u*u) * rsqrtf(fabsf(scale));
    }
    g_Wc[d*KS + t] = sum;
}

// transpose Wp1 [k][n] -> g_Wp1h [n][k], fp16
__global__ void k_wp1h(const float* __restrict__ Wp1) {
    __shared__ float t[32][33];
    int nb = blockIdx.x * 32, kb = blockIdx.y * 32;
    int tx = threadIdx.x, ty = threadIdx.y;   // (32, 8)
    #pragma unroll
    for (int i = 0; i < 32; i += 8)
        t[ty+i][tx] = Wp1[(size_t)(kb + ty + i)*BDIM + nb + tx];
    __syncthreads();
    #pragma unroll
    for (int i = 0; i < 32; i += 8)
        g_Wp1h[(size_t)(nb + ty + i)*BDIM + kb + tx] = __float2half(t[tx][ty+i]);
}

// ---------------- depthwise conv: smem-tiled, register accumulators ----------------
#define CTS 64
#define CDC 128
__global__ __launch_bounds__(512) void k_conv(const float* __restrict__ x) {
    __shared__ float tile[CTS + 18][CDC];
    int b  = blockIdx.z;
    int s0 = blockIdx.y * CTS;
    int d0 = blockIdx.x * CDC;
    int tid = threadIdx.x;

    const int NV = (CTS + 18) * (CDC / 4);
    for (int i = tid; i < NV; i += 512) {
        int r = i / (CDC/4), c4 = i % (CDC/4);
        int s = s0 - 9 + r;
        float4 v = make_float4(0.f, 0.f, 0.f, 0.f);
        if (s >= 0 && s < SLEN)
            v = *(const float4*)&x[((size_t)b*SLEN + s)*BDIM + d0 + c4*4];
        *(float4*)&tile[r][c4*4] = v;
    }
    __syncthreads();

    int dL = tid & (CDC - 1);
    int g  = tid >> 7;
    float coef[KS];
    #pragma unroll
    for (int t = 0; t < KS; t++) coef[t] = g_Wc[(d0 + dL)*KS + t];

    float acc[16];
    #pragma unroll
    for (int i = 0; i < 16; i++) acc[i] = 0.f;

    #pragma unroll
    for (int j = 0; j < 34; j++) {
        float v = tile[g*16 + j][dL];
        #pragma unroll
        for (int t = 0; t < KS; t++) {
            int s = j - t;
            if (s >= 0 && s < 16) acc[s] += v * coef[t];
        }
    }
    size_t base = ((size_t)b*SLEN + s0 + g*16)*BDIM + d0 + dL;
    #pragma unroll
    for (int i = 0; i < 16; i++)
        g_posh[base + (size_t)i*BDIM] = __float2half(acc[i]);
}

// -------- x2 = x + pos @ Wp1 + bp1 (fp16 mma.sync m16n8k16, cp.async 3-stage) --------
#define GM 128
#define GN 256
#define KCH 64
#define NCHUNK 8
#define AST 72                           // row stride in halves: 144B (16B-mult)
#define STG_H ((GM + GN) * AST)          // 27648 halves per stage
#define SM_GEMM (3*STG_H*2)              // 165888 bytes

__global__ __launch_bounds__(256) void k_gemm(const float* __restrict__ x,
                                              const float* __restrict__ bp1) {
    extern __shared__ __half smh[];
    uint32_t sb = s2u(smh);
    int tid  = threadIdx.x;
    int m0   = blockIdx.y * GM;
    int n0   = blockIdx.x * GN;
    int warp = tid >> 5, lane = tid & 31;
    int wm   = (warp & 1) * 64;          // 2 warps along m
    int wn   = (warp >> 1) * 64;         // 4 warps along n
    int gid  = lane >> 2, tig = lane & 3;

    float acc[4][8][4];
    #pragma unroll
    for (int i = 0; i < 4; i++)
        #pragma unroll
        for (int j = 0; j < 8; j++)
            #pragma unroll
            for (int r = 0; r < 4; r++) acc[i][j][r] = 0.f;

    auto load_chunk = [&](int ch, int st) {
        uint32_t ab = sb + (uint32_t)(st * STG_H) * 2u;
        uint32_t bb = ab + GM*AST*2u;
        const __half* As = g_posh + (size_t)m0 * BDIM + ch * KCH;
        #pragma unroll
        for (int it = 0; it < 4; it++) {            // A: 128 rows x 8 x 16B
            int idx = tid + it * 256;
            int r = idx >> 3, c = idx & 7;
            uint32_t dst = ab + (uint32_t)(r*144 + c*16);
            const __half* src = As + (size_t)r * BDIM + c * 8;
            asm volatile("cp.async.cg.shared.global [%0], [%1], 16;" :: "r"(dst), "l"(src));
        }
        const __half* Bs = g_Wp1h + (size_t)n0 * BDIM + ch * KCH;
        #pragma unroll
        for (int it = 0; it < 8; it++) {            // B: 256 rows x 8 x 16B
            int idx = tid + it * 256;
            int r = idx >> 3, c = idx & 7;
            uint32_t dst = bb + (uint32_t)(r*144 + c*16);
            const __half* src = Bs + (size_t)r * BDIM + c * 8;
            asm volatile("cp.async.cg.shared.global [%0], [%1], 16;" :: "r"(dst), "l"(src));
        }
        asm volatile("cp.async.commit_group;" ::: "memory");
    };

    load_chunk(0, 0);
    load_chunk(1, 1);
    load_chunk(2, 2);

    for (int i = 0; i < NCHUNK; i++) {
        int st = i % 3;
        if (i <= NCHUNK - 3)      asm volatile("cp.async.wait_group 2;" ::: "memory");
        else if (i == NCHUNK - 2) asm volatile("cp.async.wait_group 1;" ::: "memory");
        else                      asm volatile("cp.async.wait_group 0;" ::: "memory");
        __syncthreads();

        const uint32_t* Asm = (const uint32_t*)(smh + st * STG_H);            // [m][36] words
        const uint32_t* Bsm = (const uint32_t*)(smh + st * STG_H + GM*AST);   // [n][36] words
        #pragma unroll
        for (int ks = 0; ks < 4; ks++) {            // 4 x k16 per 64-k chunk
            int kw = ks * 8;                        // word offset within row
            uint32_t a[4][4], bf[8][2];
            #pragma unroll
            for (int mt = 0; mt < 4; mt++) {
                int m = wm + mt*16 + gid;
                a[mt][0] = Asm[(m    )*36 + kw + tig    ];
                a[mt][1] = Asm[(m + 8)*36 + kw + tig    ];
                a[mt][2] = Asm[(m    )*36 + kw + tig + 4];
                a[mt][3] = Asm[(m + 8)*36 + kw + tig + 4];
            }
            #pragma unroll
            for (int nt = 0; nt < 8; nt++) {
                int n = wn + nt*8 + gid;
                bf[nt][0] = Bsm[n*36 + kw + tig    ];
                bf[nt][1] = Bsm[n*36 + kw + tig + 4];
            }
            #pragma unroll
            for (int mt = 0; mt < 4; mt++)
                #pragma unroll
                for (int nt = 0; nt < 8; nt++) {
                    asm volatile(
                        "mma.sync.aligned.m16n8k16.row.col.f32.f16.f16.f32 "
                        "{%0,%1,%2,%3}, {%4,%5,%6,%7}, {%8,%9}, {%0,%1,%2,%3};\n"
                        : "+f"(acc[mt][nt][0]), "+f"(acc[mt][nt][1]),
                          "+f"(acc[mt][nt][2]), "+f"(acc[mt][nt][3])
                        : "r"(a[mt][0]), "r"(a[mt][1]), "r"(a[mt][2]), "r"(a[mt][3]),
                          "r"(bf[nt][0]), "r"(bf[nt][1]));
                }
        }
        __syncthreads();
        if (i + 3 < NCHUNK) load_chunk(i + 3, st);
    }

    // epilogue: x2 = acc + x + bp1
    #pragma unroll
    for (int mt = 0; mt < 4; mt++) {
        int mrow = m0 + wm + mt*16;
        #pragma unroll
        for (int nt = 0; nt < 8; nt++) {
            int n = n0 + wn + nt*8 + 2*tig;
            float bx = bp1[n], by = bp1[n+1];
            {
                size_t r = (size_t)(mrow + gid);
                float2 xv = *(const float2*)&x[r*BDIM + n];
                float2 o;
                o.x = acc[mt][nt][0] + xv.x + bx;
                o.y = acc[mt][nt][1] + xv.y + by;
                *(float2*)&g_x2[r*BDIM + n] = o;
            }
            {
                size_t r = (size_t)(mrow + gid + 8);
                float2 xv = *(const float2*)&x[r*BDIM + n];
                float2 o;
                o.x = acc[mt][nt][2] + xv.x + bx;
                o.y = acc[mt][nt][3] + xv.y + by;
                *(float2*)&g_x2[r*BDIM + n] = o;
            }
        }
    }
}

// ---------------- LN stats + scores + sigmoid -> attn output ----------------
__global__ __launch_bounds__(256) void k_scores(const float* __restrict__ ln_g,
                                                const float* __restrict__ ln_b,
                                                float* __restrict__ attn_out) {
    __shared__ float red[8][32][33];
    int w    = threadIdx.x >> 5;
    int lane = threadIdx.x & 31;
    int row  = blockIdx.x*8 + w;
    int dbase = lane*16;
    const float* xr = &g_x2[(size_t)row*BDIM + dbase];

    float xv[16];
    #pragma unroll
    for (int i4 = 0; i4 < 4; i4++) {
        float4 v = *(const float4*)(xr + i4*4);
        xv[i4*4+0] = v.x; xv[i4*4+1] = v.y; xv[i4*4+2] = v.z; xv[i4*4+3] = v.w;
    }
    float sum = 0.f, sq = 0.f;
    #pragma unroll
    for (int i = 0; i < 16; i++) { sum += xv[i]; sq += xv[i]*xv[i]; }
    #pragma unroll
    for (int off = 16; off; off >>= 1) {
        sum += __shfl_xor_sync(0xffffffffu, sum, off);
        sq  += __shfl_xor_sync(0xffffffffu, sq,  off);
    }
    float mean = sum * (1.f/512.f);
    float var  = sq  * (1.f/512.f) - mean*mean;
    float rstd = rsqrtf(var + 1e-5f);
    if (lane == 0) { g_stats[row*2] = mean; g_stats[row*2+1] = rstd; }

    float xn[16];
    #pragma unroll
    for (int i4 = 0; i4 < 4; i4++) {
        float4 g = *(const float4*)&ln_g[dbase + i4*4];
        float4 b = *(const float4*)&ln_b[dbase + i4*4];
        xn[i4*4+0] = (xv[i4*4+0]-mean)*rstd*g.x + b.x;
        xn[i4*4+1] = (xv[i4*4+1]-mean)*rstd*g.y + b.y;
        xn[i4*4+2] = (xv[i4*4+2]-mean)*rstd*g.z + b.z;
        xn[i4*4+3] = (xv[i4*4+3]-mean)*rstd*g.w + b.w;
    }
    float acc[32];
    #pragma unroll
    for (int c = 0; c < 32; c++) {
        const float4* wp = (const float4*)&g_WqT[c*BDIM + dbase];
        float4 w0 = __ldg(wp+0), w1 = __ldg(wp+1), w2 = __ldg(wp+2), w3 = __ldg(wp+3);
        acc[c] = xn[0]*w0.x + xn[1]*w0.y + xn[2]*w0.z + xn[3]*w0.w
               + xn[4]*w1.x + xn[5]*w1.y + xn[6]*w1.z + xn[7]*w1.w
               + xn[8]*w2.x + xn[9]*w2.y + xn[10]*w2.z + xn[11]*w2.w
               + xn[12]*w3.x + xn[13]*w3.y + xn[14]*w3.z + xn[15]*w3.w;
    }
    #pragma unroll
    for (int c = 0; c < 32; c++) red[w][c][lane] = acc[c];
    __syncwarp();
    float t = 0.f;
    #pragma unroll
    for (int j = 0; j < 32; j++) t += red[w][lane][j];
    float a = 1.f / (1.f + expf(-(t - LOGS)));
    int b = row >> 11, s = row & (SLEN-1);
    int h = lane & 15, n = lane >> 4;
    attn_out[(((size_t)b*16 + h)*2 + n)*SLEN + s] = a;
}

// ---------------- attn scalar sums ----------------
__global__ void k_attnsums(const float* __restrict__ attn) {
    int b = blockIdx.x, c = blockIdx.y;
    int n = c >> 4, h = c & 15;
    const float* ap = &attn[(((size_t)b*16 + h)*2 + n)*SLEN];
    __shared__ float s1[256], s2[256];
    float a1 = 0.f, a2 = 0.f;
    for (int s = threadIdx.x; s < SLEN; s += 256) {
        float a = ap[s];
        float m = g_stats[(b*SLEN + s)*2];
        float r = g_stats[(b*SLEN + s)*2 + 1];
        a1 += a;
        a2 += a*r*m;
    }
    s1[threadIdx.x] = a1; s2[threadIdx.x] = a2;
    __syncthreads();
    for (int off = 128; off; off >>= 1) {
        if (threadIdx.x < off) { s1[threadIdx.x] += s1[threadIdx.x+off]; s2[threadIdx.x] += s2[threadIdx.x+off]; }
        __syncthreads();
    }
    if (threadIdx.x == 0) { g_A[b*NC + c] = s1[0]; g_Mw[b*NC + c] = s2[0]; }
}

// ---------------- pooling partials ----------------
__global__ __launch_bounds__(128) void k_pool(const float* __restrict__ attn) {
    int b  = blockIdx.z;
    int s0 = blockIdx.y * 512;
    int d  = blockIdx.x * 128 + threadIdx.x;
    __shared__ float sw[32][128];
    float acc[32];
    #pragma unroll
    for (int c = 0; c < 32; c++) acc[c] = 0.f;

    for (int stile = 0; stile < 512; stile += 128) {
        int s = s0 + stile + threadIdx.x;
        float r = g_stats[(b*SLEN + s)*2 + 1];
        __syncthreads();
        #pragma unroll
        for (int c = 0; c < 32; c++) {
            int n = c >> 4, h = c & 15;
            sw[c][threadIdx.x] = attn[(((size_t)b*16 + h)*2 + n)*SLEN + s] * r;
        }
        __syncthreads();
        const float* xp = &g_x2[((size_t)b*SLEN + s0 + stile)*BDIM + d];
        #pragma unroll 4
        for (int si = 0; si < 128; si += 4) {
            float x0 = xp[(size_t)(si+0)*BDIM];
            float x1 = xp[(size_t)(si+1)*BDIM];
            float x2v = xp[(size_t)(si+2)*BDIM];
            float x3 = xp[(size_t)(si+3)*BDIM];
            #pragma unroll
            for (int c = 0; c < 32; c++) {
                float4 wv = *(float4*)&sw[c][si];
                acc[c] += wv.x*x0 + wv.y*x1 + wv.z*x2v + wv.w*x3;
            }
        }
    }
    #pragma unroll
    for (int c = 0; c < 32; c++)
        g_Ppart[(((size_t)b*4 + blockIdx.y)*NC + c)*BDIM + d] = acc[c];
}

__global__ void k_pooled(const float* __restrict__ ln_g, const float* __restrict__ ln_b) {
    int c = blockIdx.x, b = blockIdx.y, d = threadIdx.x;
    float p = 0.f;
    #pragma unroll
    for (int sc = 0; sc < 4; sc++)
        p += g_Ppart[(((size_t)b*4 + sc)*NC + c)*BDIM + d];
    float val = ln_g[d]*(p - g_Mw[b*NC + c]) + ln_b[d]*g_A[b*NC + c];
    g_pooled[((size_t)b*NC + c)*BDIM + d] = val;
}

__global__ void k_ohead(const float* __restrict__ Wkv) {
    int b = blockIdx.x, n = blockIdx.y, dp = threadIdx.x;
    int h = dp >> 5;
    const float* pp = &g_pooled[((size_t)b*NC + n*16 + h)*BDIM];
    float acc = 0.f;
    #pragma unroll 4
    for (int d = 0; d < BDIM; d++)
        acc += pp[d] * Wkv[(size_t)d*1024 + 512 + dp];
    g_ohead[(b*2 + n)*BDIM + dp] = acc;
}

__global__ void k_oproj(const float* __restrict__ Wproj, const float* __restrict__ bproj) {
    __shared__ float sv[BDIM];
    int r = blockIdx.x, dp = threadIdx.x;
    sv[dp] = g_ohead[r*BDIM + dp];
    __syncthreads();
    float acc = 0.f;
    #pragma unroll 4
    for (int d = 0; d < BDIM; d++)
        acc += sv[d] * Wproj[(size_t)d*BDIM + dp];
    g_o[r*BDIM + dp] = acc + bproj[dp];
}

__global__ void k_head(const float* __restrict__ g2, const float* __restrict__ b2,
                       const float* __restrict__ Wc1, const float* __restrict__ bc1,
                       const float* __restrict__ Wc2, const float* __restrict__ bc2,
                       float* __restrict__ out) {
    __shared__ float sx[BDIM];
    __shared__ float sr[BDIM];
    int r = blockIdx.x, j = threadIdx.x;
    float v = g_o[r*BDIM + j];
    sr[j] = v; __syncthreads();
    for (int off = 256; off; off >>= 1) {
        if (j < off) sr[j] += sr[j + off];
        __syncthreads();
    }
    float mean = sr[0] * (1.f/512.f);
    __syncthreads();
    float dv = v - mean;
    sr[j] = dv*dv; __syncthreads();
    for (int off = 256; off; off >>= 1) {
        if (j < off) sr[j] += sr[j + off];
        __syncthreads();
    }
    float rstd = rsqrtf(sr[0]*(1.f/512.f) + 1e-5f);
    __syncthreads();
    sx[j] = dv*rstd*g2[j] + b2[j];
    __syncthreads();
    float hj = bc1[j];
    #pragma unroll 4
    for (int d = 0; d < BDIM; d++)
        hj += sx[d] * Wc1[(size_t)d*BDIM + j];
    hj = fmaxf(hj, 0.f);
    sr[j] = hj * Wc2[j];
    __syncthreads();
    for (int off = 256; off; off >>= 1) {
        if (j < off) sr[j] += sr[j + off];
        __syncthreads();
    }
    if (j == 0) out[r] = sr[0] + bc2[0];
}

// ---------------- launch ----------------
extern "C" void kernel_launch(void* const* d_in, const int* in_sizes, int n_in,
                              void* d_out, int out_size) {
    const float* x      = (const float*)d_in[0];
    const float* wave1  = (const float*)d_in[1];
    const float* wave2  = (const float*)d_in[2];
    const float* wave3  = (const float*)d_in[3];
    const float* Wp1    = (const float*)d_in[4];
    const float* bp1    = (const float*)d_in[5];
    const float* cls    = (const float*)d_in[6];
    const float* ln1_g  = (const float*)d_in[7];
    const float* ln1_b  = (const float*)d_in[8];
    const float* Wq     = (const float*)d_in[9];
    const float* Wkv    = (const float*)d_in[10];
    const float* Wproj  = (const float*)d_in[11];
    const float* bproj  = (const float*)d_in[12];
    const float* ln2_g  = (const float*)d_in[13];
    const float* ln2_b  = (const float*)d_in[14];
    const float* Wc1    = (const float*)d_in[15];
    const float* bc1    = (const float*)d_in[16];
    const float* Wc2    = (const float*)d_in[17];
    const float* bc2    = (const float*)d_in[18];

    float* out  = (float*)d_out;
    float* attn = out + BATCH*2;   // logits [32,2] first, then attn [32,16,2,2048]

    static int smem_set = 0;
    if (!smem_set) {
        cudaFuncSetAttribute(k_gemm, cudaFuncAttributeMaxDynamicSharedMemorySize, SM_GEMM);
        smem_set = 1;
    }

    k_qfull<<<2, BDIM>>>(cls, Wq);
    k_weff<<<NC, BDIM>>>(Wkv);
    k_wavelet<<<KS, BDIM>>>(wave1, wave2, wave3);
    {
        dim3 g(16, 16);
        k_wp1h<<<g, dim3(32, 8)>>>(Wp1);
    }
    {
        dim3 g(BDIM/CDC, SLEN/CTS, BATCH);   // (4, 32, 32)
        k_conv<<<g, 512>>>(x);
    }
    {
        dim3 g(BDIM/GN, NROWS/GM);           // (2, 512)
        k_gemm<<<g, 256, SM_GEMM>>>(x, bp1);
    }
    k_scores<<<NROWS/8, 256>>>(ln1_g, ln1_b, attn);
    {
        dim3 g(BATCH, NC);
        k_attnsums<<<g, 256>>>(attn);
    }
    {
        dim3 g(4, 4, BATCH);
        k_pool<<<g, 128>>>(attn);
    }
    {
        dim3 g(NC, BATCH);
        k_pooled<<<g, BDIM>>>(ln1_g, ln1_b);
    }
    {
        dim3 g(BATCH, 2);
        k_ohead<<<g, BDIM>>>(Wkv);
    }
    k_oproj<<<BATCH*2, BDIM>>>(Wproj, bproj);
    k_head<<<BATCH*2, BDIM>>>(ln2_g, ln2_b, Wc1, bc1, Wc2, bc2, out);
}

// round 6
// speedup vs baseline: 1.9380x; 1.0326x over previous
#include <cuda_runtime.h>
#include <cuda_fp16.h>
#include <math.h>
#include <stdint.h>

#define BDIM 512
#define SLEN 2048
#define BATCH 32
#define NROWS (BATCH*SLEN)
#define KS 19
#define NC 32                    // NCLS * H
#define LOGS 7.6246189861594f    // log(2048)

// ---------------- scratch (static device globals; no allocs) ----------------
__device__ float  g_Wc[BDIM*KS];                   // combined wavelet kernel [d][t]
__device__ float  g_qfull[2*BDIM];                 // q rows [n][512]
__device__ float  g_WqT[NC*BDIM];                  // WqEff transposed [c][d]
__device__ __half g_Wp1h[BDIM*BDIM];               // Wp1 transposed [n][k], fp16
__device__ __half g_posh[(size_t)NROWS*BDIM];      // conv output, fp16
__device__ float  g_x2[(size_t)NROWS*BDIM];        // x + pos@Wp1 + bp1
__device__ float  g_Ppart[(size_t)BATCH*32*NC*BDIM]; // pooling partials [b][chunk][c][d]
__device__ float  g_A[BATCH*NC];                   // sum attn
__device__ float  g_Mw[BATCH*NC];                  // sum attn*rstd*mean
__device__ float  g_pooled[BATCH*NC*BDIM];         // pooled xn [b][c][d]
__device__ float  g_ohead[BATCH*2*BDIM];           // o before Wproj
__device__ float  g_o[BATCH*2*BDIM];               // o after Wproj

// ---------------- helpers ----------------
__device__ __forceinline__ uint32_t s2u(const void* p) {
    uint32_t a;
    asm("{ .reg .u64 t; cvta.to.shared.u64 t, %1; cvt.u32.u64 %0, t; }" : "=r"(a) : "l"(p));
    return a;
}

// ---------------- tiny precompute kernels ----------------
__global__ void k_qfull(const float* __restrict__ cls, const float* __restrict__ Wq) {
    int n = blockIdx.x, j = threadIdx.x;
    float acc = 0.f;
    #pragma unroll 8
    for (int d = 0; d < BDIM; d++) acc += cls[n*BDIM + d] * Wq[(size_t)d*BDIM + j];
    g_qfull[n*BDIM + j] = acc;
}

__global__ void k_weff(const float* __restrict__ Wkv) {
    int c = blockIdx.x, d = threadIdx.x;     // c = n*16 + h
    int n = c >> 4, h = c & 15;
    float acc = 0.f;
    #pragma unroll
    for (int hd = 0; hd < 32; hd++)
        acc += Wkv[(size_t)d*1024 + h*32 + hd] * g_qfull[n*BDIM + h*32 + hd];
    g_WqT[c*BDIM + d] = acc * 0.17677669529663689f;  // * HD^-0.5
    if (d < BATCH) { g_A[d*NC + c] = 0.f; g_Mw[d*NC + c] = 0.f; }
}

__global__ void k_wavelet(const float* __restrict__ w1, const float* __restrict__ w2,
                          const float* __restrict__ w3) {
    int d = threadIdx.x, t = blockIdx.x;
    const float C = 0.8673250705840776f;     // 2 / (sqrt(3) * pi^0.25)
    float xs = (float)(t - 9);
    const float* ws[3] = {w1, w2, w3};
    float sum = 0.f;
    #pragma unroll
    for (int i = 0; i < 3; i++) {
        float scale = ws[i][d];
        float shift = ws[i][BDIM + d];
        float u = (xs - shift) / scale;
        sum += C * (1.f - u*u) * expf(-0.5f*u*u) * rsqrtf(fabsf(scale));
    }
    g_Wc[d*KS + t] = sum;
}

// transpose Wp1 [k][n] -> g_Wp1h [n][k], fp16
__global__ void k_wp1h(const float* __restrict__ Wp1) {
    __shared__ float t[32][33];
    int nb = blockIdx.x * 32, kb = blockIdx.y * 32;
    int tx = threadIdx.x, ty = threadIdx.y;   // (32, 8)
    #pragma unroll
    for (int i = 0; i < 32; i += 8)
        t[ty+i][tx] = Wp1[(size_t)(kb + ty + i)*BDIM + nb + tx];
    __syncthreads();
    #pragma unroll
    for (int i = 0; i < 32; i += 8)
        g_Wp1h[(size_t)(nb + ty + i)*BDIM + kb + tx] = __float2half(t[tx][ty+i]);
}

// ---------------- depthwise conv ----------------
#define CTS 64
#define CDC 128
__global__ __launch_bounds__(512) void k_conv(const float* __restrict__ x) {
    __shared__ float tile[CTS + 18][CDC];
    int b  = blockIdx.z;
    int s0 = blockIdx.y * CTS;
    int d0 = blockIdx.x * CDC;
    int tid = threadIdx.x;

    const int NV = (CTS + 18) * (CDC / 4);
    for (int i = tid; i < NV; i += 512) {
        int r = i / (CDC/4), c4 = i % (CDC/4);
        int s = s0 - 9 + r;
        float4 v = make_float4(0.f, 0.f, 0.f, 0.f);
        if (s >= 0 && s < SLEN)
            v = *(const float4*)&x[((size_t)b*SLEN + s)*BDIM + d0 + c4*4];
        *(float4*)&tile[r][c4*4] = v;
    }
    __syncthreads();

    int dL = tid & (CDC - 1);
    int g  = tid >> 7;
    float coef[KS];
    #pragma unroll
    for (int t = 0; t < KS; t++) coef[t] = g_Wc[(d0 + dL)*KS + t];

    float acc[16];
    #pragma unroll
    for (int i = 0; i < 16; i++) acc[i] = 0.f;

    #pragma unroll
    for (int j = 0; j < 34; j++) {
        float v = tile[g*16 + j][dL];
        #pragma unroll
        for (int t = 0; t < KS; t++) {
            int s = j - t;
            if (s >= 0 && s < 16) acc[s] += v * coef[t];
        }
    }
    size_t base = ((size_t)b*SLEN + s0 + g*16)*BDIM + d0 + dL;
    #pragma unroll
    for (int i = 0; i < 16; i++)
        g_posh[base + (size_t)i*BDIM] = __float2half(acc[i]);
}

// -------- x2 = x + pos @ Wp1 + bp1 (fp16 mma.sync + ldmatrix, 2-stage cp.async) --------
#define GM 128
#define GN 256
#define KCH 64
#define NCHUNK 8
#define AST 72                           // row stride in halves: 144B
#define STG_H ((GM + GN) * AST)          // 27648 halves per stage
#define SM_GEMM (2*STG_H*2)              // 110592 bytes

__global__ __launch_bounds__(256) void k_gemm(const float* __restrict__ x,
                                              const float* __restrict__ bp1) {
    extern __shared__ __half smh[];
    uint32_t sb = s2u(smh);
    int tid  = threadIdx.x;
    int m0   = blockIdx.y * GM;
    int n0   = blockIdx.x * GN;
    int warp = tid >> 5, lane = tid & 31;
    int wm   = (warp & 1) * 64;          // 2 warps along m
    int wn   = (warp >> 1) * 64;         // 4 warps along n
    int gid  = lane >> 2, tig = lane & 3;

    float acc[4][8][4];
    #pragma unroll
    for (int i = 0; i < 4; i++)
        #pragma unroll
        for (int j = 0; j < 8; j++)
            #pragma unroll
            for (int r = 0; r < 4; r++) acc[i][j][r] = 0.f;

    auto load_chunk = [&](int ch, int st) {
        uint32_t ab = sb + (uint32_t)(st * STG_H) * 2u;
        uint32_t bb = ab + GM*AST*2u;
        const __half* As = g_posh + (size_t)m0 * BDIM + ch * KCH;
        #pragma unroll
        for (int it = 0; it < 4; it++) {            // A: 128 rows x 8 x 16B
            int idx = tid + it * 256;
            int r = idx >> 3, c = idx & 7;
            uint32_t dst = ab + (uint32_t)(r*144 + c*16);
            const __half* src = As + (size_t)r * BDIM + c * 8;
            asm volatile("cp.async.cg.shared.global [%0], [%1], 16;" :: "r"(dst), "l"(src));
        }
        const __half* Bs = g_Wp1h + (size_t)n0 * BDIM + ch * KCH;
        #pragma unroll
        for (int it = 0; it < 8; it++) {            // B: 256 rows x 8 x 16B
            int idx = tid + it * 256;
            int r = idx >> 3, c = idx & 7;
            uint32_t dst = bb + (uint32_t)(r*144 + c*16);
            const __half* src = Bs + (size_t)r * BDIM + c * 8;
            asm volatile("cp.async.cg.shared.global [%0], [%1], 16;" :: "r"(dst), "l"(src));
        }
        asm volatile("cp.async.commit_group;" ::: "memory");
    };

    load_chunk(0, 0);
    load_chunk(1, 1);

    for (int i = 0; i < NCHUNK; i++) {
        int st = i & 1;
        if (i >= NCHUNK - 1) asm volatile("cp.async.wait_group 0;" ::: "memory");
        else                 asm volatile("cp.async.wait_group 1;" ::: "memory");
        __syncthreads();

        uint32_t abase = sb + (uint32_t)(st * STG_H) * 2u;
        uint32_t bbase = abase + GM*AST*2u;
        // per-lane ldmatrix addresses (byte offsets)
        int arow_off = (lane & 7) + ((lane >> 3) & 1) * 8;
        int acol_off = (lane >> 4) * 8;              // halves
        int brow_off = (lane & 7);
        int bcol_off = ((lane >> 3) & 1) * 8;        // halves

        #pragma unroll
        for (int ks = 0; ks < 4; ks++) {
            uint32_t a[4][4], bf[8][2];
            #pragma unroll
            for (int mt = 0; mt < 4; mt++) {
                int m = wm + mt*16 + arow_off;
                uint32_t addr = abase + (uint32_t)(m*144 + (ks*16 + acol_off)*2);
                asm volatile("ldmatrix.sync.aligned.m8n8.x4.shared.b16 {%0,%1,%2,%3}, [%4];"
                             : "=r"(a[mt][0]), "=r"(a[mt][1]), "=r"(a[mt][2]), "=r"(a[mt][3])
                             : "r"(addr));
            }
            #pragma unroll
            for (int nt = 0; nt < 8; nt++) {
                int n = wn + nt*8 + brow_off;
                uint32_t addr = bbase + (uint32_t)(n*144 + (ks*16 + bcol_off)*2);
                asm volatile("ldmatrix.sync.aligned.m8n8.x2.shared.b16 {%0,%1}, [%2];"
                             : "=r"(bf[nt][0]), "=r"(bf[nt][1])
                             : "r"(addr));
            }
            #pragma unroll
            for (int mt = 0; mt < 4; mt++)
                #pragma unroll
                for (int nt = 0; nt < 8; nt++) {
                    asm volatile(
                        "mma.sync.aligned.m16n8k16.row.col.f32.f16.f16.f32 "
                        "{%0,%1,%2,%3}, {%4,%5,%6,%7}, {%8,%9}, {%0,%1,%2,%3};\n"
                        : "+f"(acc[mt][nt][0]), "+f"(acc[mt][nt][1]),
                          "+f"(acc[mt][nt][2]), "+f"(acc[mt][nt][3])
                        : "r"(a[mt][0]), "r"(a[mt][1]), "r"(a[mt][2]), "r"(a[mt][3]),
                          "r"(bf[nt][0]), "r"(bf[nt][1]));
                }
        }
        __syncthreads();
        if (i + 2 < NCHUNK) load_chunk(i + 2, st);
    }

    // epilogue: x2 = acc + x + bp1
    #pragma unroll
    for (int mt = 0; mt < 4; mt++) {
        int mrow = m0 + wm + mt*16;
        #pragma unroll
        for (int nt = 0; nt < 8; nt++) {
            int n = n0 + wn + nt*8 + 2*tig;
            float bx = bp1[n], by = bp1[n+1];
            {
                size_t r = (size_t)(mrow + gid);
                float2 xv = *(const float2*)&x[r*BDIM + n];
                float2 o;
                o.x = acc[mt][nt][0] + xv.x + bx;
                o.y = acc[mt][nt][1] + xv.y + by;
                *(float2*)&g_x2[r*BDIM + n] = o;
            }
            {
                size_t r = (size_t)(mrow + gid + 8);
                float2 xv = *(const float2*)&x[r*BDIM + n];
                float2 o;
                o.x = acc[mt][nt][2] + xv.x + bx;
                o.y = acc[mt][nt][3] + xv.y + by;
                *(float2*)&g_x2[r*BDIM + n] = o;
            }
        }
    }
}

// ------ fused: LN + scores + sigmoid + attn out + attn sums + pooling partials ------
#define FS 64
__global__ __launch_bounds__(256) void k_fused(const float* __restrict__ ln_g,
                                               const float* __restrict__ ln_b,
                                               float* __restrict__ attn_out) {
    __shared__ float red[8][32][33];    // per-warp transpose-reduce
    __shared__ float sw[32][FS];        // a * rstd  [c][s_local]
    __shared__ float sA[32], sMw[32];
    int b  = blockIdx.y;
    int s0 = blockIdx.x * FS;
    int w = threadIdx.x >> 5, lane = threadIdx.x & 31;
    int dbase = lane * 16;

    if (threadIdx.x < 32) { sA[threadIdx.x] = 0.f; sMw[threadIdx.x] = 0.f; }
    __syncthreads();

    // Phase A: per-row LN + scores + sigmoid (each warp: 8 rows)
    for (int r = 0; r < 8; r++) {
        int sl  = w*8 + r;
        int row = b*SLEN + s0 + sl;
        const float* xr = &g_x2[(size_t)row*BDIM + dbase];
        float xv[16];
        #pragma unroll
        for (int i4 = 0; i4 < 4; i4++) {
            float4 v = *(const float4*)(xr + i4*4);
            xv[i4*4+0] = v.x; xv[i4*4+1] = v.y; xv[i4*4+2] = v.z; xv[i4*4+3] = v.w;
        }
        float sum = 0.f, sq = 0.f;
        #pragma unroll
        for (int i = 0; i < 16; i++) { sum += xv[i]; sq += xv[i]*xv[i]; }
        #pragma unroll
        for (int off = 16; off; off >>= 1) {
            sum += __shfl_xor_sync(0xffffffffu, sum, off);
            sq  += __shfl_xor_sync(0xffffffffu, sq,  off);
        }
        float mean = sum * (1.f/512.f);
        float var  = sq  * (1.f/512.f) - mean*mean;
        float rstd = rsqrtf(var + 1e-5f);

        float xn[16];
        #pragma unroll
        for (int i4 = 0; i4 < 4; i4++) {
            float4 g = *(const float4*)&ln_g[dbase + i4*4];
            float4 bb = *(const float4*)&ln_b[dbase + i4*4];
            xn[i4*4+0] = (xv[i4*4+0]-mean)*rstd*g.x + bb.x;
            xn[i4*4+1] = (xv[i4*4+1]-mean)*rstd*g.y + bb.y;
            xn[i4*4+2] = (xv[i4*4+2]-mean)*rstd*g.z + bb.z;
            xn[i4*4+3] = (xv[i4*4+3]-mean)*rstd*g.w + bb.w;
        }
        float acc[32];
        #pragma unroll
        for (int c = 0; c < 32; c++) {
            const float4* wp = (const float4*)&g_WqT[c*BDIM + dbase];
            float4 w0 = __ldg(wp+0), w1 = __ldg(wp+1), w2 = __ldg(wp+2), w3 = __ldg(wp+3);
            acc[c] = xn[0]*w0.x + xn[1]*w0.y + xn[2]*w0.z + xn[3]*w0.w
                   + xn[4]*w1.x + xn[5]*w1.y + xn[6]*w1.z + xn[7]*w1.w
                   + xn[8]*w2.x + xn[9]*w2.y + xn[10]*w2.z + xn[11]*w2.w
                   + xn[12]*w3.x + xn[13]*w3.y + xn[14]*w3.z + xn[15]*w3.w;
        }
        #pragma unroll
        for (int c = 0; c < 32; c++) red[w][c][lane] = acc[c];
        __syncwarp();
        float t = 0.f;
        #pragma unroll
        for (int j = 0; j < 32; j++) t += red[w][lane][j];
        float a = 1.f / (1.f + expf(-(t - LOGS)));
        // lane == c index
        sw[lane][sl] = a * rstd;
        int h = lane & 15, n = lane >> 4;
        attn_out[(((size_t)b*16 + h)*2 + n)*SLEN + s0 + sl] = a;
        atomicAdd(&sA[lane],  a);
        atomicAdd(&sMw[lane], a * rstd * mean);
    }
    __syncthreads();
    if (threadIdx.x < 32) {
        atomicAdd(&g_A[b*NC + threadIdx.x],  sA[threadIdx.x]);
        atomicAdd(&g_Mw[b*NC + threadIdx.x], sMw[threadIdx.x]);
    }

    // Phase B: pooling partials P[c][d] = sum_s sw[c][s] * x2[s][d]
    int d0 = threadIdx.x, d1 = threadIdx.x + 256;
    float acc0[32], acc1[32];
    #pragma unroll
    for (int c = 0; c < 32; c++) { acc0[c] = 0.f; acc1[c] = 0.f; }
    const float* xp = &g_x2[((size_t)b*SLEN + s0)*BDIM];
    for (int s4 = 0; s4 < FS/4; s4++) {
        float x00 = xp[(size_t)(s4*4+0)*BDIM + d0];
        float x01 = xp[(size_t)(s4*4+1)*BDIM + d0];
        float x02 = xp[(size_t)(s4*4+2)*BDIM + d0];
        float x03 = xp[(size_t)(s4*4+3)*BDIM + d0];
        float x10 = xp[(size_t)(s4*4+0)*BDIM + d1];
        float x11 = xp[(size_t)(s4*4+1)*BDIM + d1];
        float x12 = xp[(size_t)(s4*4+2)*BDIM + d1];
        float x13 = xp[(size_t)(s4*4+3)*BDIM + d1];
        #pragma unroll
        for (int c = 0; c < 32; c++) {
            float4 wv = *(float4*)&sw[c][s4*4];
            acc0[c] += wv.x*x00 + wv.y*x01 + wv.z*x02 + wv.w*x03;
            acc1[c] += wv.x*x10 + wv.y*x11 + wv.z*x12 + wv.w*x13;
        }
    }
    size_t pbase = (((size_t)b*32 + blockIdx.x)*NC)*BDIM;
    #pragma unroll
    for (int c = 0; c < 32; c++) {
        g_Ppart[pbase + (size_t)c*BDIM + d0] = acc0[c];
        g_Ppart[pbase + (size_t)c*BDIM + d1] = acc1[c];
    }
}

// ---------------- combine partials -> pooled_xn ----------------
__global__ void k_pooled(const float* __restrict__ ln_g, const float* __restrict__ ln_b) {
    int c = blockIdx.x, b = blockIdx.y, d = threadIdx.x;
    float p = 0.f;
    #pragma unroll 8
    for (int sc = 0; sc < 32; sc++)
        p += g_Ppart[(((size_t)b*32 + sc)*NC + c)*BDIM + d];
    float val = ln_g[d]*(p - g_Mw[b*NC + c]) + ln_b[d]*g_A[b*NC + c];
    g_pooled[((size_t)b*NC + c)*BDIM + d] = val;
}

__global__ void k_ohead(const float* __restrict__ Wkv) {
    int b = blockIdx.x, n = blockIdx.y, dp = threadIdx.x;
    int h = dp >> 5;
    const float* pp = &g_pooled[((size_t)b*NC + n*16 + h)*BDIM];
    float acc = 0.f;
    #pragma unroll 4
    for (int d = 0; d < BDIM; d++)
        acc += pp[d] * Wkv[(size_t)d*1024 + 512 + dp];
    g_ohead[(b*2 + n)*BDIM + dp] = acc;
}

__global__ void k_oproj(const float* __restrict__ Wproj, const float* __restrict__ bproj) {
    __shared__ float sv[BDIM];
    int r = blockIdx.x, dp = threadIdx.x;
    sv[dp] = g_ohead[r*BDIM + dp];
    __syncthreads();
    float acc = 0.f;
    #pragma unroll 4
    for (int d = 0; d < BDIM; d++)
        acc += sv[d] * Wproj[(size_t)d*BDIM + dp];
    g_o[r*BDIM + dp] = acc + bproj[dp];
}

__global__ void k_head(const float* __restrict__ g2, const float* __restrict__ b2,
                       const float* __restrict__ Wc1, const float* __restrict__ bc1,
                       const float* __restrict__ Wc2, const float* __restrict__ bc2,
                       float* __restrict__ out) {
    __shared__ float sx[BDIM];
    __shared__ float sr[BDIM];
    int r = blockIdx.x, j = threadIdx.x;
    float v = g_o[r*BDIM + j];
    sr[j] = v; __syncthreads();
    for (int off = 256; off; off >>= 1) {
        if (j < off) sr[j] += sr[j + off];
        __syncthreads();
    }
    float mean = sr[0] * (1.f/512.f);
    __syncthreads();
    float dv = v - mean;
    sr[j] = dv*dv; __syncthreads();
    for (int off = 256; off; off >>= 1) {
        if (j < off) sr[j] += sr[j + off];
        __syncthreads();
    }
    float rstd = rsqrtf(sr[0]*(1.f/512.f) + 1e-5f);
    __syncthreads();
    sx[j] = dv*rstd*g2[j] + b2[j];
    __syncthreads();
    float hj = bc1[j];
    #pragma unroll 4
    for (int d = 0; d < BDIM; d++)
        hj += sx[d] * Wc1[(size_t)d*BDIM + j];
    hj = fmaxf(hj, 0.f);
    sr[j] = hj * Wc2[j];
    __syncthreads();
    for (int off = 256; off; off >>= 1) {
        if (j < off) sr[j] += sr[j + off];
        __syncthreads();
    }
    if (j == 0) out[r] = sr[0] + bc2[0];
}

// ---------------- launch ----------------
extern "C" void kernel_launch(void* const* d_in, const int* in_sizes, int n_in,
                              void* d_out, int out_size) {
    const float* x      = (const float*)d_in[0];
    const float* wave1  = (const float*)d_in[1];
    const float* wave2  = (const float*)d_in[2];
    const float* wave3  = (const float*)d_in[3];
    const float* Wp1    = (const float*)d_in[4];
    const float* bp1    = (const float*)d_in[5];
    const float* cls    = (const float*)d_in[6];
    const float* ln1_g  = (const float*)d_in[7];
    const float* ln1_b  = (const float*)d_in[8];
    const float* Wq     = (const float*)d_in[9];
    const float* Wkv    = (const float*)d_in[10];
    const float* Wproj  = (const float*)d_in[11];
    const float* bproj  = (const float*)d_in[12];
    const float* ln2_g  = (const float*)d_in[13];
    const float* ln2_b  = (const float*)d_in[14];
    const float* Wc1    = (const float*)d_in[15];
    const float* bc1    = (const float*)d_in[16];
    const float* Wc2    = (const float*)d_in[17];
    const float* bc2    = (const float*)d_in[18];

    float* out  = (float*)d_out;
    float* attn = out + BATCH*2;   // logits [32,2] first, then attn [32,16,2,2048]

    static int smem_set = 0;
    if (!smem_set) {
        cudaFuncSetAttribute(k_gemm, cudaFuncAttributeMaxDynamicSharedMemorySize, SM_GEMM);
        smem_set = 1;
    }

    // launch order: k_gemm in slot 4 (ncu capture slot)
    k_wavelet<<<KS, BDIM>>>(wave1, wave2, wave3);                  // 1
    {
        dim3 g(BDIM/CDC, SLEN/CTS, BATCH);
        k_conv<<<g, 512>>>(x);                                     // 2
    }
    {
        dim3 g(16, 16);
        k_wp1h<<<g, dim3(32, 8)>>>(Wp1);                           // 3
    }
    {
        dim3 g(BDIM/GN, NROWS/GM);
        k_gemm<<<g, 256, SM_GEMM>>>(x, bp1);                       // 4  <- profiled
    }
    k_qfull<<<2, BDIM>>>(cls, Wq);                                 // 5
    k_weff<<<NC, BDIM>>>(Wkv);                                     // 6
    {
        dim3 g(SLEN/FS, BATCH);                                    // (32, 32)
        k_fused<<<g, 256>>>(ln1_g, ln1_b, attn);                   // 7
    }
    {
        dim3 g(NC, BATCH);
        k_pooled<<<g, BDIM>>>(ln1_g, ln1_b);                       // 8
    }
    {
        dim3 g(BATCH, 2);
        k_ohead<<<g, BDIM>>>(Wkv);                                 // 9
    }
    k_oproj<<<BATCH*2, BDIM>>>(Wproj, bproj);                      // 10
    k_head<<<BATCH*2, BDIM>>>(ln2_g, ln2_b, Wc1, bc1, Wc2, bc2, out); // 11
}